// round 11
// baseline (speedup 1.0000x reference)
#include <cuda_runtime.h>
#include <cstdint>

// Problem constants (fixed by the reference)
#define NN 100000
#define NF 512
#define NH 128
#define NC 40
#define EMAX 3200000

// Scratch (device globals; no allocation allowed)
__device__ float  g_supp1[NN * NH];     // x @ W1          51.2 MB
__device__ float  g_supp2[NN * NC];     // x2 @ W2         16 MB
__device__ float2 g_edges[EMAX];        // CSR (col,w)     25.6 MB
__device__ int    g_rowptr[NN + 1];
__device__ int    g_cursor[NN];
__device__ int    g_deg[NN];

// Side stream + fork/join events, created at program init.
static cudaStream_t g_s1 = nullptr;
static cudaEvent_t  g_ev_fork = nullptr, g_ev_join = nullptr;
namespace {
struct StreamInit {
    StreamInit() {
        cudaStreamCreateWithFlags(&g_s1, cudaStreamNonBlocking);
        cudaEventCreateWithFlags(&g_ev_fork, cudaEventDisableTiming);
        cudaEventCreateWithFlags(&g_ev_join, cudaEventDisableTiming);
    }
};
static StreamInit g_stream_init;
}

// ---------------------------------------------------------------------------
// f32x2 packed helpers
// ---------------------------------------------------------------------------
typedef unsigned long long ull;

__device__ __forceinline__ ull ffma2(ull a, ull b, ull c) {
    ull d;
    asm("fma.rn.f32x2 %0, %1, %2, %3;" : "=l"(d) : "l"(a), "l"(b), "l"(c));
    return d;
}
__device__ __forceinline__ ull pack2(float lo, float hi) {
    ull d;
    asm("mov.b64 %0, {%1, %2};" : "=l"(d) : "f"(lo), "f"(hi));
    return d;
}
__device__ __forceinline__ void unpack2(ull v, float& lo, float& hi) {
    asm("mov.b64 {%0, %1}, %2;" : "=f"(lo), "=f"(hi) : "l"(v));
}

// ---------------------------------------------------------------------------
// GEMM1 (packed FFMA2): supp1[N,128] = x[N,512] @ W1[512,128]
// ---------------------------------------------------------------------------
#define AT_PAD 130
#define BS_PAD 132

__global__ __launch_bounds__(256) void gemm1_kernel(
    const float* __restrict__ x, const float* __restrict__ W1,
    float* __restrict__ out)
{
    __shared__ float As_t[16][AT_PAD];   // [k][row]
    __shared__ float Bs[16][BS_PAD];     // [k][col]

    const int t = threadIdx.x;
    const int wid = t >> 5, lane = t & 31;
    const int warp_m = wid & 3;
    const int warp_n = wid >> 2;
    const int r0 = warp_m * 32 + (lane & 3) * 8;
    const int c0 = warp_n * 64 + (lane >> 2) * 8;
    const int block_row = blockIdx.x * 128;

    ull acc[4][8];
#pragma unroll
    for (int p = 0; p < 4; p++)
#pragma unroll
        for (int c = 0; c < 8; c++) acc[p][c] = 0ULL;

    for (int k0 = 0; k0 < NF; k0 += 16) {
#pragma unroll
        for (int j = 0; j < 2; j++) {
            int i = t + j * 256;
            int r = i >> 2;
            int kq = (i & 3) << 2;
            float4 v = make_float4(0.f, 0.f, 0.f, 0.f);
            if (block_row + r < NN)
                v = *(const float4*)&x[(size_t)(block_row + r) * NF + k0 + kq];
            As_t[kq + 0][r] = v.x;
            As_t[kq + 1][r] = v.y;
            As_t[kq + 2][r] = v.z;
            As_t[kq + 3][r] = v.w;
        }
#pragma unroll
        for (int j = 0; j < 2; j++) {
            int i = t + j * 256;
            int kk = i >> 5;
            int c = (i & 31) << 2;
            *(float4*)&Bs[kk][c] = *(const float4*)&W1[(size_t)(k0 + kk) * NH + c];
        }
        __syncthreads();

#pragma unroll
        for (int kk = 0; kk < 16; kk++) {
            ull a2[4];
#pragma unroll
            for (int p = 0; p < 4; p++)
                a2[p] = *(const ull*)&As_t[kk][r0 + p * 2];

            float4 b04 = *(const float4*)&Bs[kk][c0];
            float4 b48 = *(const float4*)&Bs[kk][c0 + 4];
            ull b2[8];
            b2[0] = pack2(b04.x, b04.x); b2[1] = pack2(b04.y, b04.y);
            b2[2] = pack2(b04.z, b04.z); b2[3] = pack2(b04.w, b04.w);
            b2[4] = pack2(b48.x, b48.x); b2[5] = pack2(b48.y, b48.y);
            b2[6] = pack2(b48.z, b48.z); b2[7] = pack2(b48.w, b48.w);

#pragma unroll
            for (int p = 0; p < 4; p++)
#pragma unroll
                for (int c = 0; c < 8; c++)
                    acc[p][c] = ffma2(a2[p], b2[c], acc[p][c]);
        }
        __syncthreads();
    }

#pragma unroll
    for (int p = 0; p < 4; p++) {
        float lo[8], hi[8];
#pragma unroll
        for (int c = 0; c < 8; c++) unpack2(acc[p][c], lo[c], hi[c]);
        int gr0 = block_row + r0 + p * 2;
        int gr1 = gr0 + 1;
        if (gr0 < NN) {
            *(float4*)&out[(size_t)gr0 * NH + c0]     = make_float4(lo[0], lo[1], lo[2], lo[3]);
            *(float4*)&out[(size_t)gr0 * NH + c0 + 4] = make_float4(lo[4], lo[5], lo[6], lo[7]);
        }
        if (gr1 < NN) {
            *(float4*)&out[(size_t)gr1 * NH + c0]     = make_float4(hi[0], hi[1], hi[2], hi[3]);
            *(float4*)&out[(size_t)gr1 * NH + c0 + 4] = make_float4(hi[4], hi[5], hi[6], hi[7]);
        }
    }
}

// ---------------------------------------------------------------------------
// CSR build
// ---------------------------------------------------------------------------
__global__ void zero_deg_kernel(int* __restrict__ deg)
{
    int i = blockIdx.x * blockDim.x + threadIdx.x;
    if (i < NN) deg[i] = 0;
}

__global__ void hist_kernel(const int* __restrict__ er, int* __restrict__ deg, int E)
{
    int e = (blockIdx.x * blockDim.x + threadIdx.x) * 2;
    if (e + 1 < E) {
        int2 r2 = *(const int2*)&er[e];
        atomicAdd(&deg[r2.x], 1);
        atomicAdd(&deg[r2.y], 1);
    } else if (e < E) {
        atomicAdd(&deg[er[e]], 1);
    }
}

// exclusive scan over deg -> rowptr/cursor, single block, warp-shfl based.
__global__ __launch_bounds__(1024) void scan_kernel(
    const int* __restrict__ deg, int* __restrict__ rowptr,
    int* __restrict__ cursor)
{
    __shared__ int wsum[32];
    __shared__ int carry_s;
    const int t = threadIdx.x, lane = t & 31, w = t >> 5;
    if (t == 0) carry_s = 0;
    __syncthreads();

    for (int base = 0; base < NN; base += 4096) {
        int cbase = carry_s;
        int i = base + t * 4;
        int4 v = make_int4(0, 0, 0, 0);
        if (i < NN) v = *(const int4*)&deg[i];   // NN % 4 == 0
        int s = v.x + v.y + v.z + v.w;

        int inc = s;
#pragma unroll
        for (int o = 1; o < 32; o <<= 1) {
            int y = __shfl_up_sync(0xffffffffu, inc, o);
            if (lane >= o) inc += y;
        }
        if (lane == 31) wsum[w] = inc;
        __syncthreads();
        if (w == 0) {
            int ws = wsum[lane];
#pragma unroll
            for (int o = 1; o < 32; o <<= 1) {
                int y = __shfl_up_sync(0xffffffffu, ws, o);
                if (lane >= o) ws += y;
            }
            wsum[lane] = ws;
        }
        __syncthreads();

        int prefix = cbase + ((w > 0) ? wsum[w - 1] : 0) + (inc - s);
        if (i < NN) {
            int e0 = prefix;
            int e1 = e0 + v.x;
            int e2 = e1 + v.y;
            int e3 = e2 + v.z;
            int4 o4 = make_int4(e0, e1, e2, e3);
            *(int4*)&rowptr[i] = o4;
            *(int4*)&cursor[i] = o4;
        }
        __syncthreads();
        if (t == 0) carry_s += wsum[31];
        __syncthreads();
    }
    if (t == 0) rowptr[NN] = carry_s;
}

__global__ void scatter_kernel(
    const int* __restrict__ er, const int* __restrict__ ec,
    const float* __restrict__ ew, int* __restrict__ cursor,
    float2* __restrict__ edges, int E)
{
    int e = (blockIdx.x * blockDim.x + threadIdx.x) * 2;
    if (e + 1 < E) {
        int2   r2 = *(const int2*)&er[e];
        int2   c2 = *(const int2*)&ec[e];
        float2 w2 = *(const float2*)&ew[e];
        int p0 = atomicAdd(&cursor[r2.x], 1);
        edges[p0] = make_float2(__int_as_float(c2.x), w2.x);
        int p1 = atomicAdd(&cursor[r2.y], 1);
        edges[p1] = make_float2(__int_as_float(c2.y), w2.y);
    } else if (e < E) {
        int pos = atomicAdd(&cursor[er[e]], 1);
        edges[pos] = make_float2(__int_as_float(ec[e]), ew[e]);
    }
}

// ---------------------------------------------------------------------------
// SpMM1-CSR fused with bias + relu + dropout mask.
// 2 warps per row: warp-half p walks edges s+p, s+p+2, ... (4-edge unroll,
// stride 2 within the half). Odd half deposits its partial in smem; even
// half combines and runs the epilogue. Halves the per-row latency chain.
// Block = 8 warps = 4 rows. NN % 4 == 0.
// ---------------------------------------------------------------------------
__global__ __launch_bounds__(256) void spmm1_csr_kernel(
    const int* __restrict__ rowptr, const float2* __restrict__ edges,
    const float4* __restrict__ suppv, const float* __restrict__ b1,
    const float* __restrict__ mask, float* __restrict__ x2)
{
    __shared__ float4 part[4][32];

    const int wid  = threadIdx.x >> 5;   // 0..7
    const int lane = threadIdx.x & 31;
    const int rib  = wid >> 1;           // row in block 0..3
    const int half = wid & 1;            // 0 or 1
    const int row  = blockIdx.x * 4 + rib;

    const int s = rowptr[row];
    const int e = rowptr[row + 1];

    float4 acc = make_float4(0.f, 0.f, 0.f, 0.f);
    int i = s + half;
    // 4-edge unroll over this half's edges: i, i+2, i+4, i+6
    for (; i + 6 < e; i += 8) {
        float2 ed0 = __ldg(&edges[i]);
        float2 ed1 = __ldg(&edges[i + 2]);
        float2 ed2 = __ldg(&edges[i + 4]);
        float2 ed3 = __ldg(&edges[i + 6]);
        float4 g0 = __ldg(&suppv[(size_t)__float_as_int(ed0.x) * (NH / 4) + lane]);
        float4 g1 = __ldg(&suppv[(size_t)__float_as_int(ed1.x) * (NH / 4) + lane]);
        float4 g2 = __ldg(&suppv[(size_t)__float_as_int(ed2.x) * (NH / 4) + lane]);
        float4 g3 = __ldg(&suppv[(size_t)__float_as_int(ed3.x) * (NH / 4) + lane]);
        acc.x = fmaf(ed0.y, g0.x, acc.x); acc.y = fmaf(ed0.y, g0.y, acc.y);
        acc.z = fmaf(ed0.y, g0.z, acc.z); acc.w = fmaf(ed0.y, g0.w, acc.w);
        acc.x = fmaf(ed1.y, g1.x, acc.x); acc.y = fmaf(ed1.y, g1.y, acc.y);
        acc.z = fmaf(ed1.y, g1.z, acc.z); acc.w = fmaf(ed1.y, g1.w, acc.w);
        acc.x = fmaf(ed2.y, g2.x, acc.x); acc.y = fmaf(ed2.y, g2.y, acc.y);
        acc.z = fmaf(ed2.y, g2.z, acc.z); acc.w = fmaf(ed2.y, g2.w, acc.w);
        acc.x = fmaf(ed3.y, g3.x, acc.x); acc.y = fmaf(ed3.y, g3.y, acc.y);
        acc.z = fmaf(ed3.y, g3.z, acc.z); acc.w = fmaf(ed3.y, g3.w, acc.w);
    }
    for (; i < e; i += 2) {
        float2 ed = __ldg(&edges[i]);
        float4 g = __ldg(&suppv[(size_t)__float_as_int(ed.x) * (NH / 4) + lane]);
        acc.x = fmaf(ed.y, g.x, acc.x); acc.y = fmaf(ed.y, g.y, acc.y);
        acc.z = fmaf(ed.y, g.z, acc.z); acc.w = fmaf(ed.y, g.w, acc.w);
    }

    if (half == 1) part[rib][lane] = acc;
    __syncthreads();

    if (half == 0) {
        float4 o = part[rib][lane];
        acc.x += o.x; acc.y += o.y; acc.z += o.z; acc.w += o.w;

        float4 bb = *(const float4*)&b1[lane << 2];
        float4 mm = *(const float4*)&mask[(size_t)row * NH + (lane << 2)];
        float4 r;
        r.x = fmaxf(acc.x + bb.x, 0.f) * mm.x;
        r.y = fmaxf(acc.y + bb.y, 0.f) * mm.y;
        r.z = fmaxf(acc.z + bb.z, 0.f) * mm.z;
        r.w = fmaxf(acc.w + bb.w, 0.f) * mm.w;
        *(float4*)&x2[(size_t)row * NH + (lane << 2)] = r;
    }
}

// ---------------------------------------------------------------------------
// GEMM2: supp2[N,40] = x2[N,128] @ W2[128,40]. Warp-per-row, W2 in smem.
// ---------------------------------------------------------------------------
__global__ __launch_bounds__(256) void gemm2_kernel(
    const float* __restrict__ x2, const float* __restrict__ W2,
    float* __restrict__ out)
{
    __shared__ float sW2[NH * NC];  // 20 KB
    for (int i = threadIdx.x; i < NH * NC; i += blockDim.x) sW2[i] = W2[i];
    __syncthreads();

    const int lane = threadIdx.x & 31;
    const int wid  = threadIdx.x >> 5;
    const int row  = blockIdx.x * 8 + wid;
    if (row >= NN) return;

    float acc1 = 0.0f, acc2 = 0.0f;
    const float* xr = &x2[(size_t)row * NH];
#pragma unroll 8
    for (int k = 0; k < NH; k++) {
        float xv = xr[k];
        acc1 = fmaf(xv, sW2[k * NC + lane], acc1);
        if (lane < 8) acc2 = fmaf(xv, sW2[k * NC + 32 + lane], acc2);
    }
    out[(size_t)row * NC + lane] = acc1;
    if (lane < 8) out[(size_t)row * NC + 32 + lane] = acc2;
}

// ---------------------------------------------------------------------------
// SpMM2-CSR fused with bias + log_softmax.
// Lane layout: 3 edge-groups x 10 class-chunks (30 active lanes).
// ---------------------------------------------------------------------------
__global__ __launch_bounds__(256) void spmm2_lsm_kernel(
    const int* __restrict__ rowptr, const float2* __restrict__ edges,
    const float4* __restrict__ suppv, const float* __restrict__ b2,
    float* __restrict__ out)
{
    const int warp = (blockIdx.x * blockDim.x + threadIdx.x) >> 5;
    if (warp >= NN) return;
    const int lane = threadIdx.x & 31;
    const int grp  = lane / 10;            // 0,1,2 active; 3 = lanes 30,31 idle
    const int cls  = lane - grp * 10;      // 0..9
    const bool in3 = (grp < 3);

    const int s = rowptr[warp];
    const int e = rowptr[warp + 1];

    float4 acc = make_float4(0.f, 0.f, 0.f, 0.f);
    if (in3) {
        for (int i = s + grp; i < e; i += 3) {
            float2 ed = __ldg(&edges[i]);
            float4 g = __ldg(&suppv[(size_t)__float_as_int(ed.x) * (NC / 4) + cls]);
            acc.x = fmaf(ed.y, g.x, acc.x); acc.y = fmaf(ed.y, g.y, acc.y);
            acc.z = fmaf(ed.y, g.z, acc.z); acc.w = fmaf(ed.y, g.w, acc.w);
        }
    }

    // fold groups 1,2 into lanes 0..9; both terms from the PRE-fold value
    {
        float t1x = __shfl_down_sync(0xffffffffu, acc.x, 10);
        float t1y = __shfl_down_sync(0xffffffffu, acc.y, 10);
        float t1z = __shfl_down_sync(0xffffffffu, acc.z, 10);
        float t1w = __shfl_down_sync(0xffffffffu, acc.w, 10);
        float t2x = __shfl_down_sync(0xffffffffu, acc.x, 20);
        float t2y = __shfl_down_sync(0xffffffffu, acc.y, 20);
        float t2z = __shfl_down_sync(0xffffffffu, acc.z, 20);
        float t2w = __shfl_down_sync(0xffffffffu, acc.w, 20);
        acc.x += t1x + t2x;
        acc.y += t1y + t2y;
        acc.z += t1z + t2z;
        acc.w += t1w + t2w;
    }

    const bool act = (lane < 10);
    float4 v = make_float4(0.f, 0.f, 0.f, 0.f);
    float m = -3.4e38f;
    if (act) {
        float4 bb = *(const float4*)&b2[lane << 2];
        v.x = acc.x + bb.x; v.y = acc.y + bb.y;
        v.z = acc.z + bb.z; v.w = acc.w + bb.w;
        m = fmaxf(fmaxf(v.x, v.y), fmaxf(v.z, v.w));
    }
#pragma unroll
    for (int o = 16; o > 0; o >>= 1)
        m = fmaxf(m, __shfl_xor_sync(0xffffffffu, m, o));

    float sum = 0.f;
    if (act)
        sum = __expf(v.x - m) + __expf(v.y - m) + __expf(v.z - m) + __expf(v.w - m);
#pragma unroll
    for (int o = 16; o > 0; o >>= 1)
        sum += __shfl_xor_sync(0xffffffffu, sum, o);

    float lse = m + __logf(sum);
    if (act) {
        *(float4*)&out[(size_t)warp * NC + (lane << 2)] =
            make_float4(v.x - lse, v.y - lse, v.z - lse, v.w - lse);
    }
}

// ---------------------------------------------------------------------------
extern "C" void kernel_launch(void* const* d_in, const int* in_sizes, int n_in,
                              void* d_out, int out_size)
{
    const float* x    = (const float*)d_in[0];
    const int*   er   = (const int*)  d_in[1];
    const int*   ec   = (const int*)  d_in[2];
    const float* ew   = (const float*)d_in[3];
    const float* W1   = (const float*)d_in[4];
    const float* b1   = (const float*)d_in[5];
    const float* W2   = (const float*)d_in[6];
    const float* b2   = (const float*)d_in[7];
    const float* mask = (const float*)d_in[8];
    const int E = in_sizes[1];

    float* out_lsm = (float*)d_out;                   // [N, 40]
    float* out_x2  = (float*)d_out + (size_t)NN * NC; // [N, 128]

    float *supp1, *supp2; float2* edges; int *rowptr, *cursor, *deg;
    cudaGetSymbolAddress((void**)&supp1,  g_supp1);
    cudaGetSymbolAddress((void**)&supp2,  g_supp2);
    cudaGetSymbolAddress((void**)&edges,  g_edges);
    cudaGetSymbolAddress((void**)&rowptr, g_rowptr);
    cudaGetSymbolAddress((void**)&cursor, g_cursor);
    cudaGetSymbolAddress((void**)&deg,    g_deg);

    const bool fork = (g_s1 != nullptr);
    cudaStream_t s1 = fork ? g_s1 : (cudaStream_t)0;

    // Fork: CSR build on side stream, gemm1 on main (null) stream.
    if (fork) {
        cudaEventRecord(g_ev_fork, 0);
        cudaStreamWaitEvent(s1, g_ev_fork, 0);
    }

    zero_deg_kernel<<<(NN + 255) / 256, 256, 0, s1>>>(deg);
    hist_kernel<<<(E / 2 + 255) / 256, 256, 0, s1>>>(er, deg, E);
    scan_kernel<<<1, 1024, 0, s1>>>(deg, rowptr, cursor);
    scatter_kernel<<<(E / 2 + 255) / 256, 256, 0, s1>>>(er, ec, ew, cursor, edges, E);

    gemm1_kernel<<<(NN + 127) / 128, 256>>>(x, W1, supp1);

    // Join before spmm1 (needs both supp1 and CSR).
    if (fork) {
        cudaEventRecord(g_ev_join, s1);
        cudaStreamWaitEvent(0, g_ev_join, 0);
    }

    spmm1_csr_kernel<<<NN / 4, 256>>>(
        rowptr, edges, (const float4*)supp1, b1, mask, out_x2);

    gemm2_kernel<<<(NN + 7) / 8, 256>>>(out_x2, W2, supp2);
    spmm2_lsm_kernel<<<(NN * 32 + 255) / 256, 256>>>(
        rowptr, edges, (const float4*)supp2, b2, out_lsm);
}

// round 12
// speedup vs baseline: 1.0456x; 1.0456x over previous
#include <cuda_runtime.h>
#include <cstdint>

// Problem constants (fixed by the reference)
#define NN 100000
#define NF 512
#define NH 128
#define NC 40
#define EMAX 3200000

// Scratch (device globals; no allocation allowed)
__device__ float  g_supp1[NN * NH];     // x @ W1          51.2 MB
__device__ float  g_supp2[NN * NC];     // x2 @ W2         16 MB
__device__ float2 g_edges[EMAX];        // CSR (col,w)     25.6 MB
__device__ int    g_rowptr[NN + 1];
__device__ int    g_cursor[NN];
__device__ int    g_deg[NN];

// Side stream + fork/join events, created at program init.
static cudaStream_t g_s1 = nullptr;
static cudaEvent_t  g_ev_fork = nullptr, g_ev_join = nullptr;
namespace {
struct StreamInit {
    StreamInit() {
        cudaStreamCreateWithFlags(&g_s1, cudaStreamNonBlocking);
        cudaEventCreateWithFlags(&g_ev_fork, cudaEventDisableTiming);
        cudaEventCreateWithFlags(&g_ev_join, cudaEventDisableTiming);
    }
};
static StreamInit g_stream_init;
}

// ---------------------------------------------------------------------------
// f32x2 packed helpers
// ---------------------------------------------------------------------------
typedef unsigned long long ull;

__device__ __forceinline__ ull ffma2(ull a, ull b, ull c) {
    ull d;
    asm("fma.rn.f32x2 %0, %1, %2, %3;" : "=l"(d) : "l"(a), "l"(b), "l"(c));
    return d;
}
__device__ __forceinline__ ull pack2(float lo, float hi) {
    ull d;
    asm("mov.b64 %0, {%1, %2};" : "=l"(d) : "f"(lo), "f"(hi));
    return d;
}
__device__ __forceinline__ void unpack2(ull v, float& lo, float& hi) {
    asm("mov.b64 {%0, %1}, %2;" : "=f"(lo), "=f"(hi) : "l"(v));
}

// ---------------------------------------------------------------------------
// GEMM1 (packed FFMA2, double-buffered + register-staged pipeline):
//   supp1[N,128] = x[N,512] @ W1[512,128]
// CTA tile 128x128, BK=16, 8 warps (4M x 2N), thread tile 8 rows x 8 cols.
// Chunk ch+1's global loads are issued at the top of chunk ch's compute,
// hiding LDG latency under ~2048 cyc of FFMA2; one __syncthreads per chunk.
// ---------------------------------------------------------------------------
#define AT_PAD 130
#define BS_PAD 132
#define NCHUNK (NF / 16)   // 32

__global__ __launch_bounds__(256) void gemm1_kernel(
    const float* __restrict__ x, const float* __restrict__ W1,
    float* __restrict__ out)
{
    __shared__ float As_t[2][16][AT_PAD];   // [buf][k][row]
    __shared__ float Bs[2][16][BS_PAD];     // [buf][k][col]

    const int t = threadIdx.x;
    const int wid = t >> 5, lane = t & 31;
    const int warp_m = wid & 3;
    const int warp_n = wid >> 2;
    const int r0 = warp_m * 32 + (lane & 3) * 8;
    const int c0 = warp_n * 64 + (lane >> 2) * 8;
    const int block_row = blockIdx.x * 128;

    // load-index precompute (2 float4 for A, 2 for B per thread)
    const int a_r0  = t >> 2;                 // rows t/4, +64
    const int a_kq  = (t & 3) << 2;
    const int b_kk0 = t >> 5;                 // k rows t/32, +8
    const int b_c   = (t & 31) << 2;

    float4 aReg[2], bReg[2];

    // prologue: load chunk 0 into registers
    {
        const int k0 = 0;
#pragma unroll
        for (int j = 0; j < 2; j++) {
            int r = a_r0 + j * 64;
            aReg[j] = make_float4(0.f, 0.f, 0.f, 0.f);
            if (block_row + r < NN)
                aReg[j] = *(const float4*)&x[(size_t)(block_row + r) * NF + k0 + a_kq];
            bReg[j] = *(const float4*)&W1[(size_t)(k0 + b_kk0 + j * 8) * NH + b_c];
        }
    }
    // store chunk 0 into buffer 0
#pragma unroll
    for (int j = 0; j < 2; j++) {
        int r = a_r0 + j * 64;
        As_t[0][a_kq + 0][r] = aReg[j].x;
        As_t[0][a_kq + 1][r] = aReg[j].y;
        As_t[0][a_kq + 2][r] = aReg[j].z;
        As_t[0][a_kq + 3][r] = aReg[j].w;
        *(float4*)&Bs[0][b_kk0 + j * 8][b_c] = bReg[j];
    }
    __syncthreads();

    ull acc[4][8];
#pragma unroll
    for (int p = 0; p < 4; p++)
#pragma unroll
        for (int c = 0; c < 8; c++) acc[p][c] = 0ULL;

    for (int ch = 0; ch < NCHUNK; ch++) {
        const int buf = ch & 1;

        // issue next chunk's global loads (latency hidden under compute)
        if (ch + 1 < NCHUNK) {
            const int k0 = (ch + 1) * 16;
#pragma unroll
            for (int j = 0; j < 2; j++) {
                int r = a_r0 + j * 64;
                aReg[j] = make_float4(0.f, 0.f, 0.f, 0.f);
                if (block_row + r < NN)
                    aReg[j] = *(const float4*)&x[(size_t)(block_row + r) * NF + k0 + a_kq];
                bReg[j] = *(const float4*)&W1[(size_t)(k0 + b_kk0 + j * 8) * NH + b_c];
            }
        }

        // compute on current buffer
#pragma unroll
        for (int kk = 0; kk < 16; kk++) {
            ull a2[4];
#pragma unroll
            for (int p = 0; p < 4; p++)
                a2[p] = *(const ull*)&As_t[buf][kk][r0 + p * 2];

            float4 b04 = *(const float4*)&Bs[buf][kk][c0];
            float4 b48 = *(const float4*)&Bs[buf][kk][c0 + 4];
            ull b2[8];
            b2[0] = pack2(b04.x, b04.x); b2[1] = pack2(b04.y, b04.y);
            b2[2] = pack2(b04.z, b04.z); b2[3] = pack2(b04.w, b04.w);
            b2[4] = pack2(b48.x, b48.x); b2[5] = pack2(b48.y, b48.y);
            b2[6] = pack2(b48.z, b48.z); b2[7] = pack2(b48.w, b48.w);

#pragma unroll
            for (int p = 0; p < 4; p++)
#pragma unroll
                for (int c = 0; c < 8; c++)
                    acc[p][c] = ffma2(a2[p], b2[c], acc[p][c]);
        }

        // stage next chunk into the other buffer, then one sync
        if (ch + 1 < NCHUNK) {
            const int nb = buf ^ 1;
#pragma unroll
            for (int j = 0; j < 2; j++) {
                int r = a_r0 + j * 64;
                As_t[nb][a_kq + 0][r] = aReg[j].x;
                As_t[nb][a_kq + 1][r] = aReg[j].y;
                As_t[nb][a_kq + 2][r] = aReg[j].z;
                As_t[nb][a_kq + 3][r] = aReg[j].w;
                *(float4*)&Bs[nb][b_kk0 + j * 8][b_c] = bReg[j];
            }
            __syncthreads();
        }
    }

#pragma unroll
    for (int p = 0; p < 4; p++) {
        float lo[8], hi[8];
#pragma unroll
        for (int c = 0; c < 8; c++) unpack2(acc[p][c], lo[c], hi[c]);
        int gr0 = block_row + r0 + p * 2;
        int gr1 = gr0 + 1;
        if (gr0 < NN) {
            *(float4*)&out[(size_t)gr0 * NH + c0]     = make_float4(lo[0], lo[1], lo[2], lo[3]);
            *(float4*)&out[(size_t)gr0 * NH + c0 + 4] = make_float4(lo[4], lo[5], lo[6], lo[7]);
        }
        if (gr1 < NN) {
            *(float4*)&out[(size_t)gr1 * NH + c0]     = make_float4(hi[0], hi[1], hi[2], hi[3]);
            *(float4*)&out[(size_t)gr1 * NH + c0 + 4] = make_float4(hi[4], hi[5], hi[6], hi[7]);
        }
    }
}

// ---------------------------------------------------------------------------
// CSR build
// ---------------------------------------------------------------------------
__global__ void zero_deg_kernel(int* __restrict__ deg)
{
    int i = blockIdx.x * blockDim.x + threadIdx.x;
    if (i < NN) deg[i] = 0;
}

__global__ void hist_kernel(const int* __restrict__ er, int* __restrict__ deg, int E)
{
    int e = (blockIdx.x * blockDim.x + threadIdx.x) * 2;
    if (e + 1 < E) {
        int2 r2 = *(const int2*)&er[e];
        atomicAdd(&deg[r2.x], 1);
        atomicAdd(&deg[r2.y], 1);
    } else if (e < E) {
        atomicAdd(&deg[er[e]], 1);
    }
}

// exclusive scan over deg -> rowptr/cursor, single block, warp-shfl based.
__global__ __launch_bounds__(1024) void scan_kernel(
    const int* __restrict__ deg, int* __restrict__ rowptr,
    int* __restrict__ cursor)
{
    __shared__ int wsum[32];
    __shared__ int carry_s;
    const int t = threadIdx.x, lane = t & 31, w = t >> 5;
    if (t == 0) carry_s = 0;
    __syncthreads();

    for (int base = 0; base < NN; base += 4096) {
        int cbase = carry_s;
        int i = base + t * 4;
        int4 v = make_int4(0, 0, 0, 0);
        if (i < NN) v = *(const int4*)&deg[i];   // NN % 4 == 0
        int s = v.x + v.y + v.z + v.w;

        int inc = s;
#pragma unroll
        for (int o = 1; o < 32; o <<= 1) {
            int y = __shfl_up_sync(0xffffffffu, inc, o);
            if (lane >= o) inc += y;
        }
        if (lane == 31) wsum[w] = inc;
        __syncthreads();
        if (w == 0) {
            int ws = wsum[lane];
#pragma unroll
            for (int o = 1; o < 32; o <<= 1) {
                int y = __shfl_up_sync(0xffffffffu, ws, o);
                if (lane >= o) ws += y;
            }
            wsum[lane] = ws;
        }
        __syncthreads();

        int prefix = cbase + ((w > 0) ? wsum[w - 1] : 0) + (inc - s);
        if (i < NN) {
            int e0 = prefix;
            int e1 = e0 + v.x;
            int e2 = e1 + v.y;
            int e3 = e2 + v.z;
            int4 o4 = make_int4(e0, e1, e2, e3);
            *(int4*)&rowptr[i] = o4;
            *(int4*)&cursor[i] = o4;
        }
        __syncthreads();
        if (t == 0) carry_s += wsum[31];
        __syncthreads();
    }
    if (t == 0) rowptr[NN] = carry_s;
}

__global__ void scatter_kernel(
    const int* __restrict__ er, const int* __restrict__ ec,
    const float* __restrict__ ew, int* __restrict__ cursor,
    float2* __restrict__ edges, int E)
{
    int e = (blockIdx.x * blockDim.x + threadIdx.x) * 2;
    if (e + 1 < E) {
        int2   r2 = *(const int2*)&er[e];
        int2   c2 = *(const int2*)&ec[e];
        float2 w2 = *(const float2*)&ew[e];
        int p0 = atomicAdd(&cursor[r2.x], 1);
        edges[p0] = make_float2(__int_as_float(c2.x), w2.x);
        int p1 = atomicAdd(&cursor[r2.y], 1);
        edges[p1] = make_float2(__int_as_float(c2.y), w2.y);
    } else if (e < E) {
        int pos = atomicAdd(&cursor[er[e]], 1);
        edges[pos] = make_float2(__int_as_float(ec[e]), ew[e]);
    }
}

// ---------------------------------------------------------------------------
// SpMM1-CSR fused with bias + relu + dropout mask (4-edge unroll, R10 form)
// ---------------------------------------------------------------------------
__global__ __launch_bounds__(256) void spmm1_csr_kernel(
    const int* __restrict__ rowptr, const float2* __restrict__ edges,
    const float4* __restrict__ suppv, const float* __restrict__ b1,
    const float* __restrict__ mask, float* __restrict__ x2)
{
    const int warp = (blockIdx.x * blockDim.x + threadIdx.x) >> 5;
    if (warp >= NN) return;
    const int lane = threadIdx.x & 31;

    const int s = rowptr[warp];
    const int e = rowptr[warp + 1];

    float4 acc = make_float4(0.f, 0.f, 0.f, 0.f);
    int i = s;
    for (; i + 4 <= e; i += 4) {
        float2 ed0 = __ldg(&edges[i]);
        float2 ed1 = __ldg(&edges[i + 1]);
        float2 ed2 = __ldg(&edges[i + 2]);
        float2 ed3 = __ldg(&edges[i + 3]);
        float4 g0 = __ldg(&suppv[(size_t)__float_as_int(ed0.x) * (NH / 4) + lane]);
        float4 g1 = __ldg(&suppv[(size_t)__float_as_int(ed1.x) * (NH / 4) + lane]);
        float4 g2 = __ldg(&suppv[(size_t)__float_as_int(ed2.x) * (NH / 4) + lane]);
        float4 g3 = __ldg(&suppv[(size_t)__float_as_int(ed3.x) * (NH / 4) + lane]);
        acc.x = fmaf(ed0.y, g0.x, acc.x); acc.y = fmaf(ed0.y, g0.y, acc.y);
        acc.z = fmaf(ed0.y, g0.z, acc.z); acc.w = fmaf(ed0.y, g0.w, acc.w);
        acc.x = fmaf(ed1.y, g1.x, acc.x); acc.y = fmaf(ed1.y, g1.y, acc.y);
        acc.z = fmaf(ed1.y, g1.z, acc.z); acc.w = fmaf(ed1.y, g1.w, acc.w);
        acc.x = fmaf(ed2.y, g2.x, acc.x); acc.y = fmaf(ed2.y, g2.y, acc.y);
        acc.z = fmaf(ed2.y, g2.z, acc.z); acc.w = fmaf(ed2.y, g2.w, acc.w);
        acc.x = fmaf(ed3.y, g3.x, acc.x); acc.y = fmaf(ed3.y, g3.y, acc.y);
        acc.z = fmaf(ed3.y, g3.z, acc.z); acc.w = fmaf(ed3.y, g3.w, acc.w);
    }
    for (; i < e; i++) {
        float2 ed = __ldg(&edges[i]);
        float4 g = __ldg(&suppv[(size_t)__float_as_int(ed.x) * (NH / 4) + lane]);
        acc.x = fmaf(ed.y, g.x, acc.x); acc.y = fmaf(ed.y, g.y, acc.y);
        acc.z = fmaf(ed.y, g.z, acc.z); acc.w = fmaf(ed.y, g.w, acc.w);
    }

    float4 bb = *(const float4*)&b1[lane << 2];
    float4 mm = *(const float4*)&mask[(size_t)warp * NH + (lane << 2)];
    float4 r;
    r.x = fmaxf(acc.x + bb.x, 0.f) * mm.x;
    r.y = fmaxf(acc.y + bb.y, 0.f) * mm.y;
    r.z = fmaxf(acc.z + bb.z, 0.f) * mm.z;
    r.w = fmaxf(acc.w + bb.w, 0.f) * mm.w;
    *(float4*)&x2[(size_t)warp * NH + (lane << 2)] = r;
}

// ---------------------------------------------------------------------------
// GEMM2: supp2[N,40] = x2[N,128] @ W2[128,40]. Warp-per-row, W2 in smem.
// ---------------------------------------------------------------------------
__global__ __launch_bounds__(256) void gemm2_kernel(
    const float* __restrict__ x2, const float* __restrict__ W2,
    float* __restrict__ out)
{
    __shared__ float sW2[NH * NC];  // 20 KB
    for (int i = threadIdx.x; i < NH * NC; i += blockDim.x) sW2[i] = W2[i];
    __syncthreads();

    const int lane = threadIdx.x & 31;
    const int wid  = threadIdx.x >> 5;
    const int row  = blockIdx.x * 8 + wid;
    if (row >= NN) return;

    float acc1 = 0.0f, acc2 = 0.0f;
    const float* xr = &x2[(size_t)row * NH];
#pragma unroll 8
    for (int k = 0; k < NH; k++) {
        float xv = xr[k];
        acc1 = fmaf(xv, sW2[k * NC + lane], acc1);
        if (lane < 8) acc2 = fmaf(xv, sW2[k * NC + 32 + lane], acc2);
    }
    out[(size_t)row * NC + lane] = acc1;
    if (lane < 8) out[(size_t)row * NC + 32 + lane] = acc2;
}

// ---------------------------------------------------------------------------
// SpMM2-CSR fused with bias + log_softmax.
// Lane layout: 3 edge-groups x 10 class-chunks (30 active lanes).
// ---------------------------------------------------------------------------
__global__ __launch_bounds__(256) void spmm2_lsm_kernel(
    const int* __restrict__ rowptr, const float2* __restrict__ edges,
    const float4* __restrict__ suppv, const float* __restrict__ b2,
    float* __restrict__ out)
{
    const int warp = (blockIdx.x * blockDim.x + threadIdx.x) >> 5;
    if (warp >= NN) return;
    const int lane = threadIdx.x & 31;
    const int grp  = lane / 10;            // 0,1,2 active; 3 = lanes 30,31 idle
    const int cls  = lane - grp * 10;      // 0..9
    const bool in3 = (grp < 3);

    const int s = rowptr[warp];
    const int e = rowptr[warp + 1];

    float4 acc = make_float4(0.f, 0.f, 0.f, 0.f);
    if (in3) {
        for (int i = s + grp; i < e; i += 3) {
            float2 ed = __ldg(&edges[i]);
            float4 g = __ldg(&suppv[(size_t)__float_as_int(ed.x) * (NC / 4) + cls]);
            acc.x = fmaf(ed.y, g.x, acc.x); acc.y = fmaf(ed.y, g.y, acc.y);
            acc.z = fmaf(ed.y, g.z, acc.z); acc.w = fmaf(ed.y, g.w, acc.w);
        }
    }

    // fold groups 1,2 into lanes 0..9; both terms from the PRE-fold value
    {
        float t1x = __shfl_down_sync(0xffffffffu, acc.x, 10);
        float t1y = __shfl_down_sync(0xffffffffu, acc.y, 10);
        float t1z = __shfl_down_sync(0xffffffffu, acc.z, 10);
        float t1w = __shfl_down_sync(0xffffffffu, acc.w, 10);
        float t2x = __shfl_down_sync(0xffffffffu, acc.x, 20);
        float t2y = __shfl_down_sync(0xffffffffu, acc.y, 20);
        float t2z = __shfl_down_sync(0xffffffffu, acc.z, 20);
        float t2w = __shfl_down_sync(0xffffffffu, acc.w, 20);
        acc.x += t1x + t2x;
        acc.y += t1y + t2y;
        acc.z += t1z + t2z;
        acc.w += t1w + t2w;
    }

    const bool act = (lane < 10);
    float4 v = make_float4(0.f, 0.f, 0.f, 0.f);
    float m = -3.4e38f;
    if (act) {
        float4 bb = *(const float4*)&b2[lane << 2];
        v.x = acc.x + bb.x; v.y = acc.y + bb.y;
        v.z = acc.z + bb.z; v.w = acc.w + bb.w;
        m = fmaxf(fmaxf(v.x, v.y), fmaxf(v.z, v.w));
    }
#pragma unroll
    for (int o = 16; o > 0; o >>= 1)
        m = fmaxf(m, __shfl_xor_sync(0xffffffffu, m, o));

    float sum = 0.f;
    if (act)
        sum = __expf(v.x - m) + __expf(v.y - m) + __expf(v.z - m) + __expf(v.w - m);
#pragma unroll
    for (int o = 16; o > 0; o >>= 1)
        sum += __shfl_xor_sync(0xffffffffu, sum, o);

    float lse = m + __logf(sum);
    if (act) {
        *(float4*)&out[(size_t)warp * NC + (lane << 2)] =
            make_float4(v.x - lse, v.y - lse, v.z - lse, v.w - lse);
    }
}

// ---------------------------------------------------------------------------
extern "C" void kernel_launch(void* const* d_in, const int* in_sizes, int n_in,
                              void* d_out, int out_size)
{
    const float* x    = (const float*)d_in[0];
    const int*   er   = (const int*)  d_in[1];
    const int*   ec   = (const int*)  d_in[2];
    const float* ew   = (const float*)d_in[3];
    const float* W1   = (const float*)d_in[4];
    const float* b1   = (const float*)d_in[5];
    const float* W2   = (const float*)d_in[6];
    const float* b2   = (const float*)d_in[7];
    const float* mask = (const float*)d_in[8];
    const int E = in_sizes[1];

    float* out_lsm = (float*)d_out;                   // [N, 40]
    float* out_x2  = (float*)d_out + (size_t)NN * NC; // [N, 128]

    float *supp1, *supp2; float2* edges; int *rowptr, *cursor, *deg;
    cudaGetSymbolAddress((void**)&supp1,  g_supp1);
    cudaGetSymbolAddress((void**)&supp2,  g_supp2);
    cudaGetSymbolAddress((void**)&edges,  g_edges);
    cudaGetSymbolAddress((void**)&rowptr, g_rowptr);
    cudaGetSymbolAddress((void**)&cursor, g_cursor);
    cudaGetSymbolAddress((void**)&deg,    g_deg);

    const bool fork = (g_s1 != nullptr);
    cudaStream_t s1 = fork ? g_s1 : (cudaStream_t)0;

    // Fork: CSR build on side stream, gemm1 on main (null) stream.
    if (fork) {
        cudaEventRecord(g_ev_fork, 0);
        cudaStreamWaitEvent(s1, g_ev_fork, 0);
    }

    zero_deg_kernel<<<(NN + 255) / 256, 256, 0, s1>>>(deg);
    hist_kernel<<<(E / 2 + 255) / 256, 256, 0, s1>>>(er, deg, E);
    scan_kernel<<<1, 1024, 0, s1>>>(deg, rowptr, cursor);
    scatter_kernel<<<(E / 2 + 255) / 256, 256, 0, s1>>>(er, ec, ew, cursor, edges, E);

    gemm1_kernel<<<(NN + 127) / 128, 256>>>(x, W1, supp1);

    // Join before spmm1 (needs both supp1 and CSR).
    if (fork) {
        cudaEventRecord(g_ev_join, s1);
        cudaStreamWaitEvent(0, g_ev_join, 0);
    }

    spmm1_csr_kernel<<<(NN * 32 + 255) / 256, 256>>>(
        rowptr, edges, (const float4*)supp1, b1, mask, out_x2);

    gemm2_kernel<<<(NN + 7) / 8, 256>>>(out_x2, W2, supp2);
    spmm2_lsm_kernel<<<(NN * 32 + 255) / 256, 256>>>(
        rowptr, edges, (const float4*)supp2, b2, out_lsm);
}

// round 13
// speedup vs baseline: 1.1186x; 1.0698x over previous
#include <cuda_runtime.h>
#include <cstdint>

// Problem constants (fixed by the reference)
#define NN 100000
#define NF 512
#define NH 128
#define NC 40
#define EMAX 3200000

// Scratch (device globals; no allocation allowed)
__device__ float  g_supp1[NN * NH];     // x @ W1          51.2 MB
__device__ float  g_supp2[NN * NC];     // x2 @ W2         16 MB
__device__ float2 g_edges[EMAX];        // CSR (col,w)     25.6 MB
__device__ int    g_rowptr[NN + 1];
__device__ int    g_cursor[NN];
__device__ int    g_deg[NN];

// Side stream + fork/join events, created at program init.
static cudaStream_t g_s1 = nullptr;
static cudaEvent_t  g_ev_fork = nullptr, g_ev_join = nullptr;
namespace {
struct StreamInit {
    StreamInit() {
        cudaStreamCreateWithFlags(&g_s1, cudaStreamNonBlocking);
        cudaEventCreateWithFlags(&g_ev_fork, cudaEventDisableTiming);
        cudaEventCreateWithFlags(&g_ev_join, cudaEventDisableTiming);
    }
};
static StreamInit g_stream_init;
}

// ---------------------------------------------------------------------------
// f32x2 packed helpers
// ---------------------------------------------------------------------------
typedef unsigned long long ull;

__device__ __forceinline__ ull ffma2(ull a, ull b, ull c) {
    ull d;
    asm("fma.rn.f32x2 %0, %1, %2, %3;" : "=l"(d) : "l"(a), "l"(b), "l"(c));
    return d;
}
__device__ __forceinline__ ull pack2(float lo, float hi) {
    ull d;
    asm("mov.b64 %0, {%1, %2};" : "=l"(d) : "f"(lo), "f"(hi));
    return d;
}
__device__ __forceinline__ void unpack2(ull v, float& lo, float& hi) {
    asm("mov.b64 {%0, %1}, %2;" : "=f"(lo), "=f"(hi) : "l"(v));
}

// ---------------------------------------------------------------------------
// GEMM1 (packed FFMA2): supp1[N,128] = x[N,512] @ W1[512,128]   (R10 form)
// ---------------------------------------------------------------------------
#define AT_PAD 130
#define BS_PAD 132

__global__ __launch_bounds__(256) void gemm1_kernel(
    const float* __restrict__ x, const float* __restrict__ W1,
    float* __restrict__ out)
{
    __shared__ float As_t[16][AT_PAD];   // [k][row]
    __shared__ float Bs[16][BS_PAD];     // [k][col]

    const int t = threadIdx.x;
    const int wid = t >> 5, lane = t & 31;
    const int warp_m = wid & 3;
    const int warp_n = wid >> 2;
    const int r0 = warp_m * 32 + (lane & 3) * 8;
    const int c0 = warp_n * 64 + (lane >> 2) * 8;
    const int block_row = blockIdx.x * 128;

    ull acc[4][8];
#pragma unroll
    for (int p = 0; p < 4; p++)
#pragma unroll
        for (int c = 0; c < 8; c++) acc[p][c] = 0ULL;

    for (int k0 = 0; k0 < NF; k0 += 16) {
#pragma unroll
        for (int j = 0; j < 2; j++) {
            int i = t + j * 256;
            int r = i >> 2;
            int kq = (i & 3) << 2;
            float4 v = make_float4(0.f, 0.f, 0.f, 0.f);
            if (block_row + r < NN)
                v = *(const float4*)&x[(size_t)(block_row + r) * NF + k0 + kq];
            As_t[kq + 0][r] = v.x;
            As_t[kq + 1][r] = v.y;
            As_t[kq + 2][r] = v.z;
            As_t[kq + 3][r] = v.w;
        }
#pragma unroll
        for (int j = 0; j < 2; j++) {
            int i = t + j * 256;
            int kk = i >> 5;
            int c = (i & 31) << 2;
            *(float4*)&Bs[kk][c] = *(const float4*)&W1[(size_t)(k0 + kk) * NH + c];
        }
        __syncthreads();

#pragma unroll
        for (int kk = 0; kk < 16; kk++) {
            ull a2[4];
#pragma unroll
            for (int p = 0; p < 4; p++)
                a2[p] = *(const ull*)&As_t[kk][r0 + p * 2];

            float4 b04 = *(const float4*)&Bs[kk][c0];
            float4 b48 = *(const float4*)&Bs[kk][c0 + 4];
            ull b2[8];
            b2[0] = pack2(b04.x, b04.x); b2[1] = pack2(b04.y, b04.y);
            b2[2] = pack2(b04.z, b04.z); b2[3] = pack2(b04.w, b04.w);
            b2[4] = pack2(b48.x, b48.x); b2[5] = pack2(b48.y, b48.y);
            b2[6] = pack2(b48.z, b48.z); b2[7] = pack2(b48.w, b48.w);

#pragma unroll
            for (int p = 0; p < 4; p++)
#pragma unroll
                for (int c = 0; c < 8; c++)
                    acc[p][c] = ffma2(a2[p], b2[c], acc[p][c]);
        }
        __syncthreads();
    }

#pragma unroll
    for (int p = 0; p < 4; p++) {
        float lo[8], hi[8];
#pragma unroll
        for (int c = 0; c < 8; c++) unpack2(acc[p][c], lo[c], hi[c]);
        int gr0 = block_row + r0 + p * 2;
        int gr1 = gr0 + 1;
        if (gr0 < NN) {
            *(float4*)&out[(size_t)gr0 * NH + c0]     = make_float4(lo[0], lo[1], lo[2], lo[3]);
            *(float4*)&out[(size_t)gr0 * NH + c0 + 4] = make_float4(lo[4], lo[5], lo[6], lo[7]);
        }
        if (gr1 < NN) {
            *(float4*)&out[(size_t)gr1 * NH + c0]     = make_float4(hi[0], hi[1], hi[2], hi[3]);
            *(float4*)&out[(size_t)gr1 * NH + c0 + 4] = make_float4(hi[4], hi[5], hi[6], hi[7]);
        }
    }
}

// ---------------------------------------------------------------------------
// CSR build
// ---------------------------------------------------------------------------
__global__ void zero_deg_kernel(int* __restrict__ deg)
{
    int i = blockIdx.x * blockDim.x + threadIdx.x;
    if (i < NN) deg[i] = 0;
}

__global__ void hist_kernel(const int* __restrict__ er, int* __restrict__ deg, int E)
{
    int e = (blockIdx.x * blockDim.x + threadIdx.x) * 2;
    if (e + 1 < E) {
        int2 r2 = *(const int2*)&er[e];
        atomicAdd(&deg[r2.x], 1);
        atomicAdd(&deg[r2.y], 1);
    } else if (e < E) {
        atomicAdd(&deg[er[e]], 1);
    }
}

// exclusive scan over deg -> rowptr/cursor, single block, warp-shfl based.
__global__ __launch_bounds__(1024) void scan_kernel(
    const int* __restrict__ deg, int* __restrict__ rowptr,
    int* __restrict__ cursor)
{
    __shared__ int wsum[32];
    __shared__ int carry_s;
    const int t = threadIdx.x, lane = t & 31, w = t >> 5;
    if (t == 0) carry_s = 0;
    __syncthreads();

    for (int base = 0; base < NN; base += 4096) {
        int cbase = carry_s;
        int i = base + t * 4;
        int4 v = make_int4(0, 0, 0, 0);
        if (i < NN) v = *(const int4*)&deg[i];   // NN % 4 == 0
        int s = v.x + v.y + v.z + v.w;

        int inc = s;
#pragma unroll
        for (int o = 1; o < 32; o <<= 1) {
            int y = __shfl_up_sync(0xffffffffu, inc, o);
            if (lane >= o) inc += y;
        }
        if (lane == 31) wsum[w] = inc;
        __syncthreads();
        if (w == 0) {
            int ws = wsum[lane];
#pragma unroll
            for (int o = 1; o < 32; o <<= 1) {
                int y = __shfl_up_sync(0xffffffffu, ws, o);
                if (lane >= o) ws += y;
            }
            wsum[lane] = ws;
        }
        __syncthreads();

        int prefix = cbase + ((w > 0) ? wsum[w - 1] : 0) + (inc - s);
        if (i < NN) {
            int e0 = prefix;
            int e1 = e0 + v.x;
            int e2 = e1 + v.y;
            int e3 = e2 + v.z;
            int4 o4 = make_int4(e0, e1, e2, e3);
            *(int4*)&rowptr[i] = o4;
            *(int4*)&cursor[i] = o4;
        }
        __syncthreads();
        if (t == 0) carry_s += wsum[31];
        __syncthreads();
    }
    if (t == 0) rowptr[NN] = carry_s;
}

__global__ void scatter_kernel(
    const int* __restrict__ er, const int* __restrict__ ec,
    const float* __restrict__ ew, int* __restrict__ cursor,
    float2* __restrict__ edges, int E)
{
    int e = (blockIdx.x * blockDim.x + threadIdx.x) * 2;
    if (e + 1 < E) {
        int2   r2 = *(const int2*)&er[e];
        int2   c2 = *(const int2*)&ec[e];
        float2 w2 = *(const float2*)&ew[e];
        int p0 = atomicAdd(&cursor[r2.x], 1);
        edges[p0] = make_float2(__int_as_float(c2.x), w2.x);
        int p1 = atomicAdd(&cursor[r2.y], 1);
        edges[p1] = make_float2(__int_as_float(c2.y), w2.y);
    } else if (e < E) {
        int pos = atomicAdd(&cursor[er[e]], 1);
        edges[pos] = make_float2(__int_as_float(ec[e]), ew[e]);
    }
}

// ---------------------------------------------------------------------------
// SpMM1-CSR fused with bias + relu + dropout mask + GEMM2.
// Warp computes its x2 row (spmm1 epilogue), writes it to d_out, stages it
// in smem, then runs gemm2's warp-per-row loop against W2 (staged per block).
// Deletes the separate gemm2 kernel and its 51MB global x2 re-read.
// Block = 8 warps = 8 rows; grid = NN/8 (NN % 8 == 0).
// ---------------------------------------------------------------------------
__global__ __launch_bounds__(256) void spmm1_gemm2_kernel(
    const int* __restrict__ rowptr, const float2* __restrict__ edges,
    const float4* __restrict__ suppv, const float* __restrict__ b1,
    const float* __restrict__ mask, const float* __restrict__ W2,
    float* __restrict__ x2, float* __restrict__ supp2)
{
    __shared__ float sW2[NH * NC];   // 20 KB
    __shared__ float sx2[8][NH];     // 4 KB, one row per warp

    // stage W2 once per block
    for (int i = threadIdx.x; i < NH * NC; i += blockDim.x) sW2[i] = W2[i];
    __syncthreads();

    const int wid  = threadIdx.x >> 5;
    const int lane = threadIdx.x & 31;
    const int row  = blockIdx.x * 8 + wid;

    const int s = rowptr[row];
    const int e = rowptr[row + 1];

    // ---- spmm1 gather (R10 form, 4-edge unroll)
    float4 acc = make_float4(0.f, 0.f, 0.f, 0.f);
    int i = s;
    for (; i + 4 <= e; i += 4) {
        float2 ed0 = __ldg(&edges[i]);
        float2 ed1 = __ldg(&edges[i + 1]);
        float2 ed2 = __ldg(&edges[i + 2]);
        float2 ed3 = __ldg(&edges[i + 3]);
        float4 g0 = __ldg(&suppv[(size_t)__float_as_int(ed0.x) * (NH / 4) + lane]);
        float4 g1 = __ldg(&suppv[(size_t)__float_as_int(ed1.x) * (NH / 4) + lane]);
        float4 g2 = __ldg(&suppv[(size_t)__float_as_int(ed2.x) * (NH / 4) + lane]);
        float4 g3 = __ldg(&suppv[(size_t)__float_as_int(ed3.x) * (NH / 4) + lane]);
        acc.x = fmaf(ed0.y, g0.x, acc.x); acc.y = fmaf(ed0.y, g0.y, acc.y);
        acc.z = fmaf(ed0.y, g0.z, acc.z); acc.w = fmaf(ed0.y, g0.w, acc.w);
        acc.x = fmaf(ed1.y, g1.x, acc.x); acc.y = fmaf(ed1.y, g1.y, acc.y);
        acc.z = fmaf(ed1.y, g1.z, acc.z); acc.w = fmaf(ed1.y, g1.w, acc.w);
        acc.x = fmaf(ed2.y, g2.x, acc.x); acc.y = fmaf(ed2.y, g2.y, acc.y);
        acc.z = fmaf(ed2.y, g2.z, acc.z); acc.w = fmaf(ed2.y, g2.w, acc.w);
        acc.x = fmaf(ed3.y, g3.x, acc.x); acc.y = fmaf(ed3.y, g3.y, acc.y);
        acc.z = fmaf(ed3.y, g3.z, acc.z); acc.w = fmaf(ed3.y, g3.w, acc.w);
    }
    for (; i < e; i++) {
        float2 ed = __ldg(&edges[i]);
        float4 g = __ldg(&suppv[(size_t)__float_as_int(ed.x) * (NH / 4) + lane]);
        acc.x = fmaf(ed.y, g.x, acc.x); acc.y = fmaf(ed.y, g.y, acc.y);
        acc.z = fmaf(ed.y, g.z, acc.z); acc.w = fmaf(ed.y, g.w, acc.w);
    }

    // ---- epilogue: bias + relu + mask -> x2 (global + smem stage)
    float4 bb = *(const float4*)&b1[lane << 2];
    float4 mm = *(const float4*)&mask[(size_t)row * NH + (lane << 2)];
    float4 r;
    r.x = fmaxf(acc.x + bb.x, 0.f) * mm.x;
    r.y = fmaxf(acc.y + bb.y, 0.f) * mm.y;
    r.z = fmaxf(acc.z + bb.z, 0.f) * mm.z;
    r.w = fmaxf(acc.w + bb.w, 0.f) * mm.w;
    *(float4*)&x2[(size_t)row * NH + (lane << 2)] = r;
    *(float4*)&sx2[wid][lane << 2] = r;
    __syncwarp();

    // ---- gemm2: supp2[row] = x2[row] @ W2  (same loop/order as old kernel)
    float acc1 = 0.0f, acc2 = 0.0f;
    const float* xr = sx2[wid];
#pragma unroll 8
    for (int k = 0; k < NH; k++) {
        float xv = xr[k];
        acc1 = fmaf(xv, sW2[k * NC + lane], acc1);
        if (lane < 8) acc2 = fmaf(xv, sW2[k * NC + 32 + lane], acc2);
    }
    supp2[(size_t)row * NC + lane] = acc1;
    if (lane < 8) supp2[(size_t)row * NC + 32 + lane] = acc2;
}

// ---------------------------------------------------------------------------
// SpMM2-CSR fused with bias + log_softmax.
// Lane layout: 3 edge-groups x 10 class-chunks (30 active lanes).
// ---------------------------------------------------------------------------
__global__ __launch_bounds__(256) void spmm2_lsm_kernel(
    const int* __restrict__ rowptr, const float2* __restrict__ edges,
    const float4* __restrict__ suppv, const float* __restrict__ b2,
    float* __restrict__ out)
{
    const int warp = (blockIdx.x * blockDim.x + threadIdx.x) >> 5;
    if (warp >= NN) return;
    const int lane = threadIdx.x & 31;
    const int grp  = lane / 10;            // 0,1,2 active; 3 = lanes 30,31 idle
    const int cls  = lane - grp * 10;      // 0..9
    const bool in3 = (grp < 3);

    const int s = rowptr[warp];
    const int e = rowptr[warp + 1];

    float4 acc = make_float4(0.f, 0.f, 0.f, 0.f);
    if (in3) {
        for (int i = s + grp; i < e; i += 3) {
            float2 ed = __ldg(&edges[i]);
            float4 g = __ldg(&suppv[(size_t)__float_as_int(ed.x) * (NC / 4) + cls]);
            acc.x = fmaf(ed.y, g.x, acc.x); acc.y = fmaf(ed.y, g.y, acc.y);
            acc.z = fmaf(ed.y, g.z, acc.z); acc.w = fmaf(ed.y, g.w, acc.w);
        }
    }

    // fold groups 1,2 into lanes 0..9; both terms from the PRE-fold value
    {
        float t1x = __shfl_down_sync(0xffffffffu, acc.x, 10);
        float t1y = __shfl_down_sync(0xffffffffu, acc.y, 10);
        float t1z = __shfl_down_sync(0xffffffffu, acc.z, 10);
        float t1w = __shfl_down_sync(0xffffffffu, acc.w, 10);
        float t2x = __shfl_down_sync(0xffffffffu, acc.x, 20);
        float t2y = __shfl_down_sync(0xffffffffu, acc.y, 20);
        float t2z = __shfl_down_sync(0xffffffffu, acc.z, 20);
        float t2w = __shfl_down_sync(0xffffffffu, acc.w, 20);
        acc.x += t1x + t2x;
        acc.y += t1y + t2y;
        acc.z += t1z + t2z;
        acc.w += t1w + t2w;
    }

    const bool act = (lane < 10);
    float4 v = make_float4(0.f, 0.f, 0.f, 0.f);
    float m = -3.4e38f;
    if (act) {
        float4 bb = *(const float4*)&b2[lane << 2];
        v.x = acc.x + bb.x; v.y = acc.y + bb.y;
        v.z = acc.z + bb.z; v.w = acc.w + bb.w;
        m = fmaxf(fmaxf(v.x, v.y), fmaxf(v.z, v.w));
    }
#pragma unroll
    for (int o = 16; o > 0; o >>= 1)
        m = fmaxf(m, __shfl_xor_sync(0xffffffffu, m, o));

    float sum = 0.f;
    if (act)
        sum = __expf(v.x - m) + __expf(v.y - m) + __expf(v.z - m) + __expf(v.w - m);
#pragma unroll
    for (int o = 16; o > 0; o >>= 1)
        sum += __shfl_xor_sync(0xffffffffu, sum, o);

    float lse = m + __logf(sum);
    if (act) {
        *(float4*)&out[(size_t)warp * NC + (lane << 2)] =
            make_float4(v.x - lse, v.y - lse, v.z - lse, v.w - lse);
    }
}

// ---------------------------------------------------------------------------
extern "C" void kernel_launch(void* const* d_in, const int* in_sizes, int n_in,
                              void* d_out, int out_size)
{
    const float* x    = (const float*)d_in[0];
    const int*   er   = (const int*)  d_in[1];
    const int*   ec   = (const int*)  d_in[2];
    const float* ew   = (const float*)d_in[3];
    const float* W1   = (const float*)d_in[4];
    const float* b1   = (const float*)d_in[5];
    const float* W2   = (const float*)d_in[6];
    const float* b2   = (const float*)d_in[7];
    const float* mask = (const float*)d_in[8];
    const int E = in_sizes[1];

    float* out_lsm = (float*)d_out;                   // [N, 40]
    float* out_x2  = (float*)d_out + (size_t)NN * NC; // [N, 128]

    float *supp1, *supp2; float2* edges; int *rowptr, *cursor, *deg;
    cudaGetSymbolAddress((void**)&supp1,  g_supp1);
    cudaGetSymbolAddress((void**)&supp2,  g_supp2);
    cudaGetSymbolAddress((void**)&edges,  g_edges);
    cudaGetSymbolAddress((void**)&rowptr, g_rowptr);
    cudaGetSymbolAddress((void**)&cursor, g_cursor);
    cudaGetSymbolAddress((void**)&deg,    g_deg);

    const bool fork = (g_s1 != nullptr);
    cudaStream_t s1 = fork ? g_s1 : (cudaStream_t)0;

    // Fork: CSR build on side stream, gemm1 on main (null) stream.
    if (fork) {
        cudaEventRecord(g_ev_fork, 0);
        cudaStreamWaitEvent(s1, g_ev_fork, 0);
    }

    zero_deg_kernel<<<(NN + 255) / 256, 256, 0, s1>>>(deg);
    hist_kernel<<<(E / 2 + 255) / 256, 256, 0, s1>>>(er, deg, E);
    scan_kernel<<<1, 1024, 0, s1>>>(deg, rowptr, cursor);
    scatter_kernel<<<(E / 2 + 255) / 256, 256, 0, s1>>>(er, ec, ew, cursor, edges, E);

    gemm1_kernel<<<(NN + 127) / 128, 256>>>(x, W1, supp1);

    // Join before spmm1 (needs both supp1 and CSR).
    if (fork) {
        cudaEventRecord(g_ev_join, s1);
        cudaStreamWaitEvent(0, g_ev_join, 0);
    }

    // spmm1 + gemm2 fused: writes x2 (d_out) and supp2 in one pass.
    spmm1_gemm2_kernel<<<NN / 8, 256>>>(
        rowptr, edges, (const float4*)supp1, b1, mask, W2, out_x2, supp2);

    spmm2_lsm_kernel<<<(NN * 32 + 255) / 256, 256>>>(
        rowptr, edges, (const float4*)supp2, b2, out_lsm);
}

// round 14
// speedup vs baseline: 1.1908x; 1.0645x over previous
#include <cuda_runtime.h>
#include <cstdint>

// Problem constants (fixed by the reference)
#define NN 100000
#define NF 512
#define NH 128
#define NC 40
#define EMAX 3200000

// Scratch (device globals; no allocation allowed)
__device__ float  g_supp1[NN * NH];     // x @ W1          51.2 MB
__device__ float  g_supp2[NN * NC];     // x2 @ W2         16 MB
__device__ float2 g_edges[EMAX];        // CSR (col,w)     25.6 MB
__device__ int    g_rowptr[NN + 1];
__device__ int    g_cursor[NN];
__device__ int    g_deg[NN];

// Side stream + fork/join events, created at program init.
static cudaStream_t g_s1 = nullptr;
static cudaEvent_t  g_ev_fork = nullptr, g_ev_join = nullptr;
namespace {
struct StreamInit {
    StreamInit() {
        cudaStreamCreateWithFlags(&g_s1, cudaStreamNonBlocking);
        cudaEventCreateWithFlags(&g_ev_fork, cudaEventDisableTiming);
        cudaEventCreateWithFlags(&g_ev_join, cudaEventDisableTiming);
    }
};
static StreamInit g_stream_init;
}

__device__ __forceinline__ float tf32_round(float v) {
    uint32_t u;
    asm("cvt.rna.tf32.f32 %0, %1;" : "=r"(u) : "f"(v));
    return __uint_as_float(u);
}

__device__ __forceinline__ void mma_tf32(float& d0, float& d1, float& d2, float& d3,
                                         uint32_t a0, uint32_t a1, uint32_t a2, uint32_t a3,
                                         uint32_t b0, uint32_t b1) {
    asm volatile(
        "mma.sync.aligned.m16n8k8.row.col.f32.tf32.tf32.f32 "
        "{%0,%1,%2,%3}, {%4,%5,%6,%7}, {%8,%9}, {%0,%1,%2,%3};"
        : "+f"(d0), "+f"(d1), "+f"(d2), "+f"(d3)
        : "r"(a0), "r"(a1), "r"(a2), "r"(a3), "r"(b0), "r"(b1));
}

// ---------------------------------------------------------------------------
// GEMM1 (tensor cores, single-pass tf32 mma.sync):
//   supp1[N,128] = x[N,512] @ W1[512,128]
// CTA tile M=128 x N=128, BK=16. 8 warps as 2 (M) x 4 (N).
// Warp tile 64x32 -> 4 m-frags (m16) x 4 n-frags (n8), 16 accums x4/lane.
// ---------------------------------------------------------------------------
#define APAD 20
#define BPAD 136

__global__ __launch_bounds__(256, 1) void gemm1_kernel(
    const float* __restrict__ x, const float* __restrict__ W1,
    float* __restrict__ out)
{
    __shared__ float As[128][APAD];
    __shared__ float Bs[16][BPAD];

    const int tid = threadIdx.x;
    const int wid = tid >> 5;
    const int lane = tid & 31;
    const int gid = lane >> 2;     // group id 0..7
    const int tg  = lane & 3;      // thread-in-group 0..3
    const int wm = wid >> 2;       // 0..1 -> rows wm*64
    const int wn = wid & 3;        // 0..3 -> cols wn*32
    const int row0 = blockIdx.x * 128;

    float acc[4][4][4];
#pragma unroll
    for (int f = 0; f < 4; f++)
#pragma unroll
        for (int n = 0; n < 4; n++)
#pragma unroll
            for (int q = 0; q < 4; q++) acc[f][n][q] = 0.0f;

    for (int ch = 0; ch < NF / 16; ch++) {
        // ---- stage A chunk: x[row0..row0+128)[ch*16..+16), tf32-rounded
#pragma unroll
        for (int j = 0; j < 2; j++) {
            int i = tid + j * 256;          // 0..511 float4s
            int r = i >> 2;
            int kq = (i & 3) << 2;
            float4 v = make_float4(0.f, 0.f, 0.f, 0.f);
            if (row0 + r < NN)
                v = *(const float4*)&x[(size_t)(row0 + r) * NF + ch * 16 + kq];
            As[r][kq + 0] = tf32_round(v.x);
            As[r][kq + 1] = tf32_round(v.y);
            As[r][kq + 2] = tf32_round(v.z);
            As[r][kq + 3] = tf32_round(v.w);
        }
        // ---- stage B chunk: W1[ch*16..+16)[0..128), tf32-rounded
#pragma unroll
        for (int j = 0; j < 2; j++) {
            int i = tid + j * 256;
            int kk = i >> 5;
            int c = (i & 31) << 2;
            float4 v = *(const float4*)&W1[(size_t)(ch * 16 + kk) * NH + c];
            Bs[kk][c + 0] = tf32_round(v.x);
            Bs[kk][c + 1] = tf32_round(v.y);
            Bs[kk][c + 2] = tf32_round(v.z);
            Bs[kk][c + 3] = tf32_round(v.w);
        }
        __syncthreads();

#pragma unroll
        for (int ks = 0; ks < 2; ks++) {
            const int k0 = ks * 8;
            uint32_t ah[4][4];
#pragma unroll
            for (int f = 0; f < 4; f++) {
                int r = wm * 64 + f * 16 + gid;
                ah[f][0] = __float_as_uint(As[r][k0 + tg]);
                ah[f][1] = __float_as_uint(As[r + 8][k0 + tg]);
                ah[f][2] = __float_as_uint(As[r][k0 + tg + 4]);
                ah[f][3] = __float_as_uint(As[r + 8][k0 + tg + 4]);
            }
            uint32_t bh[4][2];
#pragma unroll
            for (int n = 0; n < 4; n++) {
                int c = wn * 32 + n * 8 + gid;
                bh[n][0] = __float_as_uint(Bs[k0 + tg][c]);
                bh[n][1] = __float_as_uint(Bs[k0 + tg + 4][c]);
            }
#pragma unroll
            for (int f = 0; f < 4; f++)
#pragma unroll
                for (int n = 0; n < 4; n++)
                    mma_tf32(acc[f][n][0], acc[f][n][1], acc[f][n][2], acc[f][n][3],
                             ah[f][0], ah[f][1], ah[f][2], ah[f][3], bh[n][0], bh[n][1]);
        }
        __syncthreads();
    }

    // epilogue: c0/c1 at (row gid, col 2tg), c2/c3 at (row gid+8)
#pragma unroll
    for (int f = 0; f < 4; f++) {
        int r1 = row0 + wm * 64 + f * 16 + gid;
        int r2 = r1 + 8;
#pragma unroll
        for (int n = 0; n < 4; n++) {
            int c = wn * 32 + n * 8 + tg * 2;
            if (r1 < NN)
                *(float2*)&out[(size_t)r1 * NH + c] = make_float2(acc[f][n][0], acc[f][n][1]);
            if (r2 < NN)
                *(float2*)&out[(size_t)r2 * NH + c] = make_float2(acc[f][n][2], acc[f][n][3]);
        }
    }
}

// ---------------------------------------------------------------------------
// CSR build
// ---------------------------------------------------------------------------
__global__ void zero_deg_kernel(int* __restrict__ deg)
{
    int i = blockIdx.x * blockDim.x + threadIdx.x;
    if (i < NN) deg[i] = 0;
}

__global__ void hist_kernel(const int* __restrict__ er, int* __restrict__ deg, int E)
{
    int e = (blockIdx.x * blockDim.x + threadIdx.x) * 2;
    if (e + 1 < E) {
        int2 r2 = *(const int2*)&er[e];
        atomicAdd(&deg[r2.x], 1);
        atomicAdd(&deg[r2.y], 1);
    } else if (e < E) {
        atomicAdd(&deg[er[e]], 1);
    }
}

// exclusive scan over deg -> rowptr/cursor, single block, warp-shfl based.
__global__ __launch_bounds__(1024) void scan_kernel(
    const int* __restrict__ deg, int* __restrict__ rowptr,
    int* __restrict__ cursor)
{
    __shared__ int wsum[32];
    __shared__ int carry_s;
    const int t = threadIdx.x, lane = t & 31, w = t >> 5;
    if (t == 0) carry_s = 0;
    __syncthreads();

    for (int base = 0; base < NN; base += 4096) {
        int cbase = carry_s;
        int i = base + t * 4;
        int4 v = make_int4(0, 0, 0, 0);
        if (i < NN) v = *(const int4*)&deg[i];   // NN % 4 == 0
        int s = v.x + v.y + v.z + v.w;

        int inc = s;
#pragma unroll
        for (int o = 1; o < 32; o <<= 1) {
            int y = __shfl_up_sync(0xffffffffu, inc, o);
            if (lane >= o) inc += y;
        }
        if (lane == 31) wsum[w] = inc;
        __syncthreads();
        if (w == 0) {
            int ws = wsum[lane];
#pragma unroll
            for (int o = 1; o < 32; o <<= 1) {
                int y = __shfl_up_sync(0xffffffffu, ws, o);
                if (lane >= o) ws += y;
            }
            wsum[lane] = ws;
        }
        __syncthreads();

        int prefix = cbase + ((w > 0) ? wsum[w - 1] : 0) + (inc - s);
        if (i < NN) {
            int e0 = prefix;
            int e1 = e0 + v.x;
            int e2 = e1 + v.y;
            int e3 = e2 + v.z;
            int4 o4 = make_int4(e0, e1, e2, e3);
            *(int4*)&rowptr[i] = o4;
            *(int4*)&cursor[i] = o4;
        }
        __syncthreads();
        if (t == 0) carry_s += wsum[31];
        __syncthreads();
    }
    if (t == 0) rowptr[NN] = carry_s;
}

__global__ void scatter_kernel(
    const int* __restrict__ er, const int* __restrict__ ec,
    const float* __restrict__ ew, int* __restrict__ cursor,
    float2* __restrict__ edges, int E)
{
    int e = (blockIdx.x * blockDim.x + threadIdx.x) * 2;
    if (e + 1 < E) {
        int2   r2 = *(const int2*)&er[e];
        int2   c2 = *(const int2*)&ec[e];
        float2 w2 = *(const float2*)&ew[e];
        int p0 = atomicAdd(&cursor[r2.x], 1);
        edges[p0] = make_float2(__int_as_float(c2.x), w2.x);
        int p1 = atomicAdd(&cursor[r2.y], 1);
        edges[p1] = make_float2(__int_as_float(c2.y), w2.y);
    } else if (e < E) {
        int pos = atomicAdd(&cursor[er[e]], 1);
        edges[pos] = make_float2(__int_as_float(ec[e]), ew[e]);
    }
}

// ---------------------------------------------------------------------------
// SpMM1-CSR fused with bias + relu + dropout mask + GEMM2.  (R13 form)
// ---------------------------------------------------------------------------
__global__ __launch_bounds__(256) void spmm1_gemm2_kernel(
    const int* __restrict__ rowptr, const float2* __restrict__ edges,
    const float4* __restrict__ suppv, const float* __restrict__ b1,
    const float* __restrict__ mask, const float* __restrict__ W2,
    float* __restrict__ x2, float* __restrict__ supp2)
{
    __shared__ float sW2[NH * NC];   // 20 KB
    __shared__ float sx2[8][NH];     // 4 KB, one row per warp

    for (int i = threadIdx.x; i < NH * NC; i += blockDim.x) sW2[i] = W2[i];
    __syncthreads();

    const int wid  = threadIdx.x >> 5;
    const int lane = threadIdx.x & 31;
    const int row  = blockIdx.x * 8 + wid;

    const int s = rowptr[row];
    const int e = rowptr[row + 1];

    float4 acc = make_float4(0.f, 0.f, 0.f, 0.f);
    int i = s;
    for (; i + 4 <= e; i += 4) {
        float2 ed0 = __ldg(&edges[i]);
        float2 ed1 = __ldg(&edges[i + 1]);
        float2 ed2 = __ldg(&edges[i + 2]);
        float2 ed3 = __ldg(&edges[i + 3]);
        float4 g0 = __ldg(&suppv[(size_t)__float_as_int(ed0.x) * (NH / 4) + lane]);
        float4 g1 = __ldg(&suppv[(size_t)__float_as_int(ed1.x) * (NH / 4) + lane]);
        float4 g2 = __ldg(&suppv[(size_t)__float_as_int(ed2.x) * (NH / 4) + lane]);
        float4 g3 = __ldg(&suppv[(size_t)__float_as_int(ed3.x) * (NH / 4) + lane]);
        acc.x = fmaf(ed0.y, g0.x, acc.x); acc.y = fmaf(ed0.y, g0.y, acc.y);
        acc.z = fmaf(ed0.y, g0.z, acc.z); acc.w = fmaf(ed0.y, g0.w, acc.w);
        acc.x = fmaf(ed1.y, g1.x, acc.x); acc.y = fmaf(ed1.y, g1.y, acc.y);
        acc.z = fmaf(ed1.y, g1.z, acc.z); acc.w = fmaf(ed1.y, g1.w, acc.w);
        acc.x = fmaf(ed2.y, g2.x, acc.x); acc.y = fmaf(ed2.y, g2.y, acc.y);
        acc.z = fmaf(ed2.y, g2.z, acc.z); acc.w = fmaf(ed2.y, g2.w, acc.w);
        acc.x = fmaf(ed3.y, g3.x, acc.x); acc.y = fmaf(ed3.y, g3.y, acc.y);
        acc.z = fmaf(ed3.y, g3.z, acc.z); acc.w = fmaf(ed3.y, g3.w, acc.w);
    }
    for (; i < e; i++) {
        float2 ed = __ldg(&edges[i]);
        float4 g = __ldg(&suppv[(size_t)__float_as_int(ed.x) * (NH / 4) + lane]);
        acc.x = fmaf(ed.y, g.x, acc.x); acc.y = fmaf(ed.y, g.y, acc.y);
        acc.z = fmaf(ed.y, g.z, acc.z); acc.w = fmaf(ed.y, g.w, acc.w);
    }

    float4 bb = *(const float4*)&b1[lane << 2];
    float4 mm = *(const float4*)&mask[(size_t)row * NH + (lane << 2)];
    float4 r;
    r.x = fmaxf(acc.x + bb.x, 0.f) * mm.x;
    r.y = fmaxf(acc.y + bb.y, 0.f) * mm.y;
    r.z = fmaxf(acc.z + bb.z, 0.f) * mm.z;
    r.w = fmaxf(acc.w + bb.w, 0.f) * mm.w;
    *(float4*)&x2[(size_t)row * NH + (lane << 2)] = r;
    *(float4*)&sx2[wid][lane << 2] = r;
    __syncwarp();

    float acc1 = 0.0f, acc2 = 0.0f;
    const float* xr = sx2[wid];
#pragma unroll 8
    for (int k = 0; k < NH; k++) {
        float xv = xr[k];
        acc1 = fmaf(xv, sW2[k * NC + lane], acc1);
        if (lane < 8) acc2 = fmaf(xv, sW2[k * NC + 32 + lane], acc2);
    }
    supp2[(size_t)row * NC + lane] = acc1;
    if (lane < 8) supp2[(size_t)row * NC + 32 + lane] = acc2;
}

// ---------------------------------------------------------------------------
// SpMM2-CSR fused with bias + log_softmax.  (R10/R13 form)
// ---------------------------------------------------------------------------
__global__ __launch_bounds__(256) void spmm2_lsm_kernel(
    const int* __restrict__ rowptr, const float2* __restrict__ edges,
    const float4* __restrict__ suppv, const float* __restrict__ b2,
    float* __restrict__ out)
{
    const int warp = (blockIdx.x * blockDim.x + threadIdx.x) >> 5;
    if (warp >= NN) return;
    const int lane = threadIdx.x & 31;
    const int grp  = lane / 10;            // 0,1,2 active; 3 = lanes 30,31 idle
    const int cls  = lane - grp * 10;      // 0..9
    const bool in3 = (grp < 3);

    const int s = rowptr[warp];
    const int e = rowptr[warp + 1];

    float4 acc = make_float4(0.f, 0.f, 0.f, 0.f);
    if (in3) {
        for (int i = s + grp; i < e; i += 3) {
            float2 ed = __ldg(&edges[i]);
            float4 g = __ldg(&suppv[(size_t)__float_as_int(ed.x) * (NC / 4) + cls]);
            acc.x = fmaf(ed.y, g.x, acc.x); acc.y = fmaf(ed.y, g.y, acc.y);
            acc.z = fmaf(ed.y, g.z, acc.z); acc.w = fmaf(ed.y, g.w, acc.w);
        }
    }

    {
        float t1x = __shfl_down_sync(0xffffffffu, acc.x, 10);
        float t1y = __shfl_down_sync(0xffffffffu, acc.y, 10);
        float t1z = __shfl_down_sync(0xffffffffu, acc.z, 10);
        float t1w = __shfl_down_sync(0xffffffffu, acc.w, 10);
        float t2x = __shfl_down_sync(0xffffffffu, acc.x, 20);
        float t2y = __shfl_down_sync(0xffffffffu, acc.y, 20);
        float t2z = __shfl_down_sync(0xffffffffu, acc.z, 20);
        float t2w = __shfl_down_sync(0xffffffffu, acc.w, 20);
        acc.x += t1x + t2x;
        acc.y += t1y + t2y;
        acc.z += t1z + t2z;
        acc.w += t1w + t2w;
    }

    const bool act = (lane < 10);
    float4 v = make_float4(0.f, 0.f, 0.f, 0.f);
    float m = -3.4e38f;
    if (act) {
        float4 bb = *(const float4*)&b2[lane << 2];
        v.x = acc.x + bb.x; v.y = acc.y + bb.y;
        v.z = acc.z + bb.z; v.w = acc.w + bb.w;
        m = fmaxf(fmaxf(v.x, v.y), fmaxf(v.z, v.w));
    }
#pragma unroll
    for (int o = 16; o > 0; o >>= 1)
        m = fmaxf(m, __shfl_xor_sync(0xffffffffu, m, o));

    float sum = 0.f;
    if (act)
        sum = __expf(v.x - m) + __expf(v.y - m) + __expf(v.z - m) + __expf(v.w - m);
#pragma unroll
    for (int o = 16; o > 0; o >>= 1)
        sum += __shfl_xor_sync(0xffffffffu, sum, o);

    float lse = m + __logf(sum);
    if (act) {
        *(float4*)&out[(size_t)warp * NC + (lane << 2)] =
            make_float4(v.x - lse, v.y - lse, v.z - lse, v.w - lse);
    }
}

// ---------------------------------------------------------------------------
extern "C" void kernel_launch(void* const* d_in, const int* in_sizes, int n_in,
                              void* d_out, int out_size)
{
    const float* x    = (const float*)d_in[0];
    const int*   er   = (const int*)  d_in[1];
    const int*   ec   = (const int*)  d_in[2];
    const float* ew   = (const float*)d_in[3];
    const float* W1   = (const float*)d_in[4];
    const float* b1   = (const float*)d_in[5];
    const float* W2   = (const float*)d_in[6];
    const float* b2   = (const float*)d_in[7];
    const float* mask = (const float*)d_in[8];
    const int E = in_sizes[1];

    float* out_lsm = (float*)d_out;                   // [N, 40]
    float* out_x2  = (float*)d_out + (size_t)NN * NC; // [N, 128]

    float *supp1, *supp2; float2* edges; int *rowptr, *cursor, *deg;
    cudaGetSymbolAddress((void**)&supp1,  g_supp1);
    cudaGetSymbolAddress((void**)&supp2,  g_supp2);
    cudaGetSymbolAddress((void**)&edges,  g_edges);
    cudaGetSymbolAddress((void**)&rowptr, g_rowptr);
    cudaGetSymbolAddress((void**)&cursor, g_cursor);
    cudaGetSymbolAddress((void**)&deg,    g_deg);

    const bool fork = (g_s1 != nullptr);
    cudaStream_t s1 = fork ? g_s1 : (cudaStream_t)0;

    // Fork: CSR build on side stream, gemm1 on main (null) stream.
    if (fork) {
        cudaEventRecord(g_ev_fork, 0);
        cudaStreamWaitEvent(s1, g_ev_fork, 0);
    }

    zero_deg_kernel<<<(NN + 255) / 256, 256, 0, s1>>>(deg);
    hist_kernel<<<(E / 2 + 255) / 256, 256, 0, s1>>>(er, deg, E);
    scan_kernel<<<1, 1024, 0, s1>>>(deg, rowptr, cursor);
    scatter_kernel<<<(E / 2 + 255) / 256, 256, 0, s1>>>(er, ec, ew, cursor, edges, E);

    gemm1_kernel<<<(NN + 127) / 128, 256>>>(x, W1, supp1);

    // Join before spmm1 (needs both supp1 and CSR).
    if (fork) {
        cudaEventRecord(g_ev_join, s1);
        cudaStreamWaitEvent(0, g_ev_join, 0);
    }

    // spmm1 + gemm2 fused: writes x2 (d_out) and supp2 in one pass.
    spmm1_gemm2_kernel<<<NN / 8, 256>>>(
        rowptr, edges, (const float4*)supp1, b1, mask, W2, out_x2, supp2);

    spmm2_lsm_kernel<<<(NN * 32 + 255) / 256, 256>>>(
        rowptr, edges, (const float4*)supp2, b2, out_lsm);
}

// round 15
// speedup vs baseline: 1.1991x; 1.0070x over previous
#include <cuda_runtime.h>
#include <cstdint>

// Problem constants (fixed by the reference)
#define NN 100000
#define NF 512
#define NH 128
#define NC 40
#define EMAX 3200000

// Scratch (device globals; no allocation allowed)
__device__ float  g_supp1[NN * NH];     // x @ W1          51.2 MB
__device__ float  g_supp2[NN * NC];     // x2 @ W2         16 MB
__device__ float2 g_edges[EMAX];        // CSR (col,w)     25.6 MB
__device__ int    g_rowptr[NN + 1];
__device__ int    g_cursor[NN];
__device__ int    g_deg[NN];

// Side stream + fork/join events, created at program init.
static cudaStream_t g_s1 = nullptr;
static cudaEvent_t  g_ev_fork = nullptr, g_ev_join = nullptr;
namespace {
struct StreamInit {
    StreamInit() {
        cudaStreamCreateWithFlags(&g_s1, cudaStreamNonBlocking);
        cudaEventCreateWithFlags(&g_ev_fork, cudaEventDisableTiming);
        cudaEventCreateWithFlags(&g_ev_join, cudaEventDisableTiming);
    }
};
static StreamInit g_stream_init;
}

__device__ __forceinline__ float tf32_round(float v) {
    uint32_t u;
    asm("cvt.rna.tf32.f32 %0, %1;" : "=r"(u) : "f"(v));
    return __uint_as_float(u);
}

__device__ __forceinline__ void mma_tf32(float& d0, float& d1, float& d2, float& d3,
                                         uint32_t a0, uint32_t a1, uint32_t a2, uint32_t a3,
                                         uint32_t b0, uint32_t b1) {
    asm volatile(
        "mma.sync.aligned.m16n8k8.row.col.f32.tf32.tf32.f32 "
        "{%0,%1,%2,%3}, {%4,%5,%6,%7}, {%8,%9}, {%0,%1,%2,%3};"
        : "+f"(d0), "+f"(d1), "+f"(d2), "+f"(d3)
        : "r"(a0), "r"(a1), "r"(a2), "r"(a3), "r"(b0), "r"(b1));
}

// ---------------------------------------------------------------------------
// GEMM1 (tensor cores, single-pass tf32 mma.sync):  (R14 form, frozen)
//   supp1[N,128] = x[N,512] @ W1[512,128]
// ---------------------------------------------------------------------------
#define APAD 20
#define BPAD 136

__global__ __launch_bounds__(256, 1) void gemm1_kernel(
    const float* __restrict__ x, const float* __restrict__ W1,
    float* __restrict__ out)
{
    __shared__ float As[128][APAD];
    __shared__ float Bs[16][BPAD];

    const int tid = threadIdx.x;
    const int wid = tid >> 5;
    const int lane = tid & 31;
    const int gid = lane >> 2;     // group id 0..7
    const int tg  = lane & 3;      // thread-in-group 0..3
    const int wm = wid >> 2;       // 0..1 -> rows wm*64
    const int wn = wid & 3;        // 0..3 -> cols wn*32
    const int row0 = blockIdx.x * 128;

    float acc[4][4][4];
#pragma unroll
    for (int f = 0; f < 4; f++)
#pragma unroll
        for (int n = 0; n < 4; n++)
#pragma unroll
            for (int q = 0; q < 4; q++) acc[f][n][q] = 0.0f;

    for (int ch = 0; ch < NF / 16; ch++) {
#pragma unroll
        for (int j = 0; j < 2; j++) {
            int i = tid + j * 256;
            int r = i >> 2;
            int kq = (i & 3) << 2;
            float4 v = make_float4(0.f, 0.f, 0.f, 0.f);
            if (row0 + r < NN)
                v = *(const float4*)&x[(size_t)(row0 + r) * NF + ch * 16 + kq];
            As[r][kq + 0] = tf32_round(v.x);
            As[r][kq + 1] = tf32_round(v.y);
            As[r][kq + 2] = tf32_round(v.z);
            As[r][kq + 3] = tf32_round(v.w);
        }
#pragma unroll
        for (int j = 0; j < 2; j++) {
            int i = tid + j * 256;
            int kk = i >> 5;
            int c = (i & 31) << 2;
            float4 v = *(const float4*)&W1[(size_t)(ch * 16 + kk) * NH + c];
            Bs[kk][c + 0] = tf32_round(v.x);
            Bs[kk][c + 1] = tf32_round(v.y);
            Bs[kk][c + 2] = tf32_round(v.z);
            Bs[kk][c + 3] = tf32_round(v.w);
        }
        __syncthreads();

#pragma unroll
        for (int ks = 0; ks < 2; ks++) {
            const int k0 = ks * 8;
            uint32_t ah[4][4];
#pragma unroll
            for (int f = 0; f < 4; f++) {
                int r = wm * 64 + f * 16 + gid;
                ah[f][0] = __float_as_uint(As[r][k0 + tg]);
                ah[f][1] = __float_as_uint(As[r + 8][k0 + tg]);
                ah[f][2] = __float_as_uint(As[r][k0 + tg + 4]);
                ah[f][3] = __float_as_uint(As[r + 8][k0 + tg + 4]);
            }
            uint32_t bh[4][2];
#pragma unroll
            for (int n = 0; n < 4; n++) {
                int c = wn * 32 + n * 8 + gid;
                bh[n][0] = __float_as_uint(Bs[k0 + tg][c]);
                bh[n][1] = __float_as_uint(Bs[k0 + tg + 4][c]);
            }
#pragma unroll
            for (int f = 0; f < 4; f++)
#pragma unroll
                for (int n = 0; n < 4; n++)
                    mma_tf32(acc[f][n][0], acc[f][n][1], acc[f][n][2], acc[f][n][3],
                             ah[f][0], ah[f][1], ah[f][2], ah[f][3], bh[n][0], bh[n][1]);
        }
        __syncthreads();
    }

#pragma unroll
    for (int f = 0; f < 4; f++) {
        int r1 = row0 + wm * 64 + f * 16 + gid;
        int r2 = r1 + 8;
#pragma unroll
        for (int n = 0; n < 4; n++) {
            int c = wn * 32 + n * 8 + tg * 2;
            if (r1 < NN)
                *(float2*)&out[(size_t)r1 * NH + c] = make_float2(acc[f][n][0], acc[f][n][1]);
            if (r2 < NN)
                *(float2*)&out[(size_t)r2 * NH + c] = make_float2(acc[f][n][2], acc[f][n][3]);
        }
    }
}

// ---------------------------------------------------------------------------
// CSR build
// ---------------------------------------------------------------------------
__global__ void zero_deg_kernel(int* __restrict__ deg)
{
    int i = blockIdx.x * blockDim.x + threadIdx.x;
    if (i < NN) deg[i] = 0;
}

__global__ void hist_kernel(const int* __restrict__ er, int* __restrict__ deg, int E)
{
    int e = (blockIdx.x * blockDim.x + threadIdx.x) * 2;
    if (e + 1 < E) {
        int2 r2 = *(const int2*)&er[e];
        atomicAdd(&deg[r2.x], 1);
        atomicAdd(&deg[r2.y], 1);
    } else if (e < E) {
        atomicAdd(&deg[er[e]], 1);
    }
}

// exclusive scan over deg -> rowptr/cursor, single block, warp-shfl based.
__global__ __launch_bounds__(1024) void scan_kernel(
    const int* __restrict__ deg, int* __restrict__ rowptr,
    int* __restrict__ cursor)
{
    __shared__ int wsum[32];
    __shared__ int carry_s;
    const int t = threadIdx.x, lane = t & 31, w = t >> 5;
    if (t == 0) carry_s = 0;
    __syncthreads();

    for (int base = 0; base < NN; base += 4096) {
        int cbase = carry_s;
        int i = base + t * 4;
        int4 v = make_int4(0, 0, 0, 0);
        if (i < NN) v = *(const int4*)&deg[i];   // NN % 4 == 0
        int s = v.x + v.y + v.z + v.w;

        int inc = s;
#pragma unroll
        for (int o = 1; o < 32; o <<= 1) {
            int y = __shfl_up_sync(0xffffffffu, inc, o);
            if (lane >= o) inc += y;
        }
        if (lane == 31) wsum[w] = inc;
        __syncthreads();
        if (w == 0) {
            int ws = wsum[lane];
#pragma unroll
            for (int o = 1; o < 32; o <<= 1) {
                int y = __shfl_up_sync(0xffffffffu, ws, o);
                if (lane >= o) ws += y;
            }
            wsum[lane] = ws;
        }
        __syncthreads();

        int prefix = cbase + ((w > 0) ? wsum[w - 1] : 0) + (inc - s);
        if (i < NN) {
            int e0 = prefix;
            int e1 = e0 + v.x;
            int e2 = e1 + v.y;
            int e3 = e2 + v.z;
            int4 o4 = make_int4(e0, e1, e2, e3);
            *(int4*)&rowptr[i] = o4;
            *(int4*)&cursor[i] = o4;
        }
        __syncthreads();
        if (t == 0) carry_s += wsum[31];
        __syncthreads();
    }
    if (t == 0) rowptr[NN] = carry_s;
}

__global__ void scatter_kernel(
    const int* __restrict__ er, const int* __restrict__ ec,
    const float* __restrict__ ew, int* __restrict__ cursor,
    float2* __restrict__ edges, int E)
{
    int e = (blockIdx.x * blockDim.x + threadIdx.x) * 2;
    if (e + 1 < E) {
        int2   r2 = *(const int2*)&er[e];
        int2   c2 = *(const int2*)&ec[e];
        float2 w2 = *(const float2*)&ew[e];
        int p0 = atomicAdd(&cursor[r2.x], 1);
        edges[p0] = make_float2(__int_as_float(c2.x), w2.x);
        int p1 = atomicAdd(&cursor[r2.y], 1);
        edges[p1] = make_float2(__int_as_float(c2.y), w2.y);
    } else if (e < E) {
        int pos = atomicAdd(&cursor[er[e]], 1);
        edges[pos] = make_float2(__int_as_float(ec[e]), ew[e]);
    }
}

// ---------------------------------------------------------------------------
// SpMM1-CSR fused with bias + relu + dropout mask + GEMM2.
// Block = 8 warps; each warp handles 4 consecutive rows (block = 32 rows),
// amortizing the 20KB W2 staging 4x vs R13 (250MB -> 62MB of L2 traffic).
// Per-row math identical to R13 (bit-identical outputs).
// grid = NN/32 (NN % 32 == 0).
// ---------------------------------------------------------------------------
__global__ __launch_bounds__(256) void spmm1_gemm2_kernel(
    const int* __restrict__ rowptr, const float2* __restrict__ edges,
    const float4* __restrict__ suppv, const float* __restrict__ b1,
    const float* __restrict__ mask, const float* __restrict__ W2,
    float* __restrict__ x2, float* __restrict__ supp2)
{
    __shared__ float sW2[NH * NC];   // 20 KB
    __shared__ float sx2[8][NH];     // 4 KB, one row per warp

    for (int i = threadIdx.x; i < NH * NC; i += blockDim.x) sW2[i] = W2[i];
    __syncthreads();

    const int wid  = threadIdx.x >> 5;
    const int lane = threadIdx.x & 31;

    float4 bb = *(const float4*)&b1[lane << 2];

#pragma unroll 1
    for (int r4 = 0; r4 < 4; r4++) {
        const int row = blockIdx.x * 32 + wid * 4 + r4;

        const int s = rowptr[row];
        const int e = rowptr[row + 1];

        // ---- spmm1 gather (4-edge unroll, R10/R13 form)
        float4 acc = make_float4(0.f, 0.f, 0.f, 0.f);
        int i = s;
        for (; i + 4 <= e; i += 4) {
            float2 ed0 = __ldg(&edges[i]);
            float2 ed1 = __ldg(&edges[i + 1]);
            float2 ed2 = __ldg(&edges[i + 2]);
            float2 ed3 = __ldg(&edges[i + 3]);
            float4 g0 = __ldg(&suppv[(size_t)__float_as_int(ed0.x) * (NH / 4) + lane]);
            float4 g1 = __ldg(&suppv[(size_t)__float_as_int(ed1.x) * (NH / 4) + lane]);
            float4 g2 = __ldg(&suppv[(size_t)__float_as_int(ed2.x) * (NH / 4) + lane]);
            float4 g3 = __ldg(&suppv[(size_t)__float_as_int(ed3.x) * (NH / 4) + lane]);
            acc.x = fmaf(ed0.y, g0.x, acc.x); acc.y = fmaf(ed0.y, g0.y, acc.y);
            acc.z = fmaf(ed0.y, g0.z, acc.z); acc.w = fmaf(ed0.y, g0.w, acc.w);
            acc.x = fmaf(ed1.y, g1.x, acc.x); acc.y = fmaf(ed1.y, g1.y, acc.y);
            acc.z = fmaf(ed1.y, g1.z, acc.z); acc.w = fmaf(ed1.y, g1.w, acc.w);
            acc.x = fmaf(ed2.y, g2.x, acc.x); acc.y = fmaf(ed2.y, g2.y, acc.y);
            acc.z = fmaf(ed2.y, g2.z, acc.z); acc.w = fmaf(ed2.y, g2.w, acc.w);
            acc.x = fmaf(ed3.y, g3.x, acc.x); acc.y = fmaf(ed3.y, g3.y, acc.y);
            acc.z = fmaf(ed3.y, g3.z, acc.z); acc.w = fmaf(ed3.y, g3.w, acc.w);
        }
        for (; i < e; i++) {
            float2 ed = __ldg(&edges[i]);
            float4 g = __ldg(&suppv[(size_t)__float_as_int(ed.x) * (NH / 4) + lane]);
            acc.x = fmaf(ed.y, g.x, acc.x); acc.y = fmaf(ed.y, g.y, acc.y);
            acc.z = fmaf(ed.y, g.z, acc.z); acc.w = fmaf(ed.y, g.w, acc.w);
        }

        // ---- epilogue: bias + relu + mask -> x2 (global + smem stage)
        float4 mm = *(const float4*)&mask[(size_t)row * NH + (lane << 2)];
        float4 r;
        r.x = fmaxf(acc.x + bb.x, 0.f) * mm.x;
        r.y = fmaxf(acc.y + bb.y, 0.f) * mm.y;
        r.z = fmaxf(acc.z + bb.z, 0.f) * mm.z;
        r.w = fmaxf(acc.w + bb.w, 0.f) * mm.w;
        *(float4*)&x2[(size_t)row * NH + (lane << 2)] = r;
        *(float4*)&sx2[wid][lane << 2] = r;
        __syncwarp();

        // ---- gemm2: supp2[row] = x2[row] @ W2  (same loop/order as before)
        float acc1 = 0.0f, acc2 = 0.0f;
        const float* xr = sx2[wid];
#pragma unroll 8
        for (int k = 0; k < NH; k++) {
            float xv = xr[k];
            acc1 = fmaf(xv, sW2[k * NC + lane], acc1);
            if (lane < 8) acc2 = fmaf(xv, sW2[k * NC + 32 + lane], acc2);
        }
        supp2[(size_t)row * NC + lane] = acc1;
        if (lane < 8) supp2[(size_t)row * NC + 32 + lane] = acc2;
        __syncwarp();
    }
}

// ---------------------------------------------------------------------------
// SpMM2-CSR fused with bias + log_softmax.  (R10/R13 form, frozen)
// ---------------------------------------------------------------------------
__global__ __launch_bounds__(256) void spmm2_lsm_kernel(
    const int* __restrict__ rowptr, const float2* __restrict__ edges,
    const float4* __restrict__ suppv, const float* __restrict__ b2,
    float* __restrict__ out)
{
    const int warp = (blockIdx.x * blockDim.x + threadIdx.x) >> 5;
    if (warp >= NN) return;
    const int lane = threadIdx.x & 31;
    const int grp  = lane / 10;            // 0,1,2 active; 3 = lanes 30,31 idle
    const int cls  = lane - grp * 10;      // 0..9
    const bool in3 = (grp < 3);

    const int s = rowptr[warp];
    const int e = rowptr[warp + 1];

    float4 acc = make_float4(0.f, 0.f, 0.f, 0.f);
    if (in3) {
        for (int i = s + grp; i < e; i += 3) {
            float2 ed = __ldg(&edges[i]);
            float4 g = __ldg(&suppv[(size_t)__float_as_int(ed.x) * (NC / 4) + cls]);
            acc.x = fmaf(ed.y, g.x, acc.x); acc.y = fmaf(ed.y, g.y, acc.y);
            acc.z = fmaf(ed.y, g.z, acc.z); acc.w = fmaf(ed.y, g.w, acc.w);
        }
    }

    {
        float t1x = __shfl_down_sync(0xffffffffu, acc.x, 10);
        float t1y = __shfl_down_sync(0xffffffffu, acc.y, 10);
        float t1z = __shfl_down_sync(0xffffffffu, acc.z, 10);
        float t1w = __shfl_down_sync(0xffffffffu, acc.w, 10);
        float t2x = __shfl_down_sync(0xffffffffu, acc.x, 20);
        float t2y = __shfl_down_sync(0xffffffffu, acc.y, 20);
        float t2z = __shfl_down_sync(0xffffffffu, acc.z, 20);
        float t2w = __shfl_down_sync(0xffffffffu, acc.w, 20);
        acc.x += t1x + t2x;
        acc.y += t1y + t2y;
        acc.z += t1z + t2z;
        acc.w += t1w + t2w;
    }

    const bool act = (lane < 10);
    float4 v = make_float4(0.f, 0.f, 0.f, 0.f);
    float m = -3.4e38f;
    if (act) {
        float4 bb = *(const float4*)&b2[lane << 2];
        v.x = acc.x + bb.x; v.y = acc.y + bb.y;
        v.z = acc.z + bb.z; v.w = acc.w + bb.w;
        m = fmaxf(fmaxf(v.x, v.y), fmaxf(v.z, v.w));
    }
#pragma unroll
    for (int o = 16; o > 0; o >>= 1)
        m = fmaxf(m, __shfl_xor_sync(0xffffffffu, m, o));

    float sum = 0.f;
    if (act)
        sum = __expf(v.x - m) + __expf(v.y - m) + __expf(v.z - m) + __expf(v.w - m);
#pragma unroll
    for (int o = 16; o > 0; o >>= 1)
        sum += __shfl_xor_sync(0xffffffffu, sum, o);

    float lse = m + __logf(sum);
    if (act) {
        *(float4*)&out[(size_t)warp * NC + (lane << 2)] =
            make_float4(v.x - lse, v.y - lse, v.z - lse, v.w - lse);
    }
}

// ---------------------------------------------------------------------------
extern "C" void kernel_launch(void* const* d_in, const int* in_sizes, int n_in,
                              void* d_out, int out_size)
{
    const float* x    = (const float*)d_in[0];
    const int*   er   = (const int*)  d_in[1];
    const int*   ec   = (const int*)  d_in[2];
    const float* ew   = (const float*)d_in[3];
    const float* W1   = (const float*)d_in[4];
    const float* b1   = (const float*)d_in[5];
    const float* W2   = (const float*)d_in[6];
    const float* b2   = (const float*)d_in[7];
    const float* mask = (const float*)d_in[8];
    const int E = in_sizes[1];

    float* out_lsm = (float*)d_out;                   // [N, 40]
    float* out_x2  = (float*)d_out + (size_t)NN * NC; // [N, 128]

    float *supp1, *supp2; float2* edges; int *rowptr, *cursor, *deg;
    cudaGetSymbolAddress((void**)&supp1,  g_supp1);
    cudaGetSymbolAddress((void**)&supp2,  g_supp2);
    cudaGetSymbolAddress((void**)&edges,  g_edges);
    cudaGetSymbolAddress((void**)&rowptr, g_rowptr);
    cudaGetSymbolAddress((void**)&cursor, g_cursor);
    cudaGetSymbolAddress((void**)&deg,    g_deg);

    const bool fork = (g_s1 != nullptr);
    cudaStream_t s1 = fork ? g_s1 : (cudaStream_t)0;

    // Fork: CSR build on side stream, gemm1 on main (null) stream.
    if (fork) {
        cudaEventRecord(g_ev_fork, 0);
        cudaStreamWaitEvent(s1, g_ev_fork, 0);
    }

    zero_deg_kernel<<<(NN + 255) / 256, 256, 0, s1>>>(deg);
    hist_kernel<<<(E / 2 + 255) / 256, 256, 0, s1>>>(er, deg, E);
    scan_kernel<<<1, 1024, 0, s1>>>(deg, rowptr, cursor);
    scatter_kernel<<<(E / 2 + 255) / 256, 256, 0, s1>>>(er, ec, ew, cursor, edges, E);

    gemm1_kernel<<<(NN + 127) / 128, 256>>>(x, W1, supp1);

    // Join before spmm1 (needs both supp1 and CSR).
    if (fork) {
        cudaEventRecord(g_ev_join, s1);
        cudaStreamWaitEvent(0, g_ev_join, 0);
    }

    // spmm1 + gemm2 fused: writes x2 (d_out) and supp2 in one pass.
    spmm1_gemm2_kernel<<<NN / 32, 256>>>(
        rowptr, edges, (const float4*)supp1, b1, mask, W2, out_x2, supp2);

    spmm2_lsm_kernel<<<(NN * 32 + 255) / 256, 256>>>(
        rowptr, edges, (const float4*)supp2, b2, out_lsm);
}

// round 16
// speedup vs baseline: 1.3226x; 1.1030x over previous
#include <cuda_runtime.h>
#include <cstdint>

// Problem constants (fixed by the reference)
#define NN 100000
#define NF 512
#define NH 128
#define NC 40
#define EMAX 3200000

// Scratch (device globals; no allocation allowed)
__device__ float  g_supp1[NN * NH];     // x @ W1          51.2 MB
__device__ float  g_supp2[NN * NC];     // x2 @ W2         16 MB
__device__ float2 g_edges[EMAX];        // CSR (col,w)     25.6 MB
__device__ int    g_rowptr[NN + 1];
__device__ int    g_cursor[NN];
__device__ int    g_deg[NN];

// Side stream + fork/join events, created at program init.
static cudaStream_t g_s1 = nullptr;
static cudaEvent_t  g_ev_fork = nullptr, g_ev_join = nullptr;
namespace {
struct StreamInit {
    StreamInit() {
        cudaStreamCreateWithFlags(&g_s1, cudaStreamNonBlocking);
        cudaEventCreateWithFlags(&g_ev_fork, cudaEventDisableTiming);
        cudaEventCreateWithFlags(&g_ev_join, cudaEventDisableTiming);
    }
};
static StreamInit g_stream_init;
}

__device__ __forceinline__ float tf32_round(float v) {
    uint32_t u;
    asm("cvt.rna.tf32.f32 %0, %1;" : "=r"(u) : "f"(v));
    return __uint_as_float(u);
}

__device__ __forceinline__ void mma_tf32(float& d0, float& d1, float& d2, float& d3,
                                         uint32_t a0, uint32_t a1, uint32_t a2, uint32_t a3,
                                         uint32_t b0, uint32_t b1) {
    asm volatile(
        "mma.sync.aligned.m16n8k8.row.col.f32.tf32.tf32.f32 "
        "{%0,%1,%2,%3}, {%4,%5,%6,%7}, {%8,%9}, {%0,%1,%2,%3};"
        : "+f"(d0), "+f"(d1), "+f"(d2), "+f"(d3)
        : "r"(a0), "r"(a1), "r"(a2), "r"(a3), "r"(b0), "r"(b1));
}

// ---------------------------------------------------------------------------
// GEMM1 (tensor cores, single-pass tf32 mma.sync), BK=32:
//   supp1[N,128] = x[N,512] @ W1[512,128]
// CTA tile M=128 x N=128, BK=32 (16 chunks). 8 warps as 2 (M) x 4 (N).
// Warp tile 64x32 -> 4 m-frags (m16) x 4 n-frags (n8); 4 k-steps per chunk.
// Same k-step MMA sequence as R14 -> bit-identical supp1.
// ---------------------------------------------------------------------------
#define APAD 36
#define BPAD 136

__global__ __launch_bounds__(256, 1) void gemm1_kernel(
    const float* __restrict__ x, const float* __restrict__ W1,
    float* __restrict__ out)
{
    __shared__ float As[128][APAD];   // 18.0 KB
    __shared__ float Bs[32][BPAD];    // 17.4 KB

    const int tid = threadIdx.x;
    const int wid = tid >> 5;
    const int lane = tid & 31;
    const int gid = lane >> 2;     // group id 0..7
    const int tg  = lane & 3;      // thread-in-group 0..3
    const int wm = wid >> 2;       // 0..1 -> rows wm*64
    const int wn = wid & 3;        // 0..3 -> cols wn*32
    const int row0 = blockIdx.x * 128;

    float acc[4][4][4];
#pragma unroll
    for (int f = 0; f < 4; f++)
#pragma unroll
        for (int n = 0; n < 4; n++)
#pragma unroll
            for (int q = 0; q < 4; q++) acc[f][n][q] = 0.0f;

    for (int ch = 0; ch < NF / 32; ch++) {
        // ---- stage A chunk: x[row0..row0+128)[ch*32..+32), tf32-rounded
        // 128 rows x 32 k = 1024 float4, 4 per thread
#pragma unroll
        for (int j = 0; j < 4; j++) {
            int i = tid + j * 256;
            int r = i >> 3;               // 8 float4 per row
            int kq = (i & 7) << 2;
            float4 v = make_float4(0.f, 0.f, 0.f, 0.f);
            if (row0 + r < NN)
                v = *(const float4*)&x[(size_t)(row0 + r) * NF + ch * 32 + kq];
            As[r][kq + 0] = tf32_round(v.x);
            As[r][kq + 1] = tf32_round(v.y);
            As[r][kq + 2] = tf32_round(v.z);
            As[r][kq + 3] = tf32_round(v.w);
        }
        // ---- stage B chunk: W1[ch*32..+32)[0..128), tf32-rounded
        // 32 k x 128 cols = 1024 float4, 4 per thread
#pragma unroll
        for (int j = 0; j < 4; j++) {
            int i = tid + j * 256;
            int kk = i >> 5;
            int c = (i & 31) << 2;
            float4 v = *(const float4*)&W1[(size_t)(ch * 32 + kk) * NH + c];
            Bs[kk][c + 0] = tf32_round(v.x);
            Bs[kk][c + 1] = tf32_round(v.y);
            Bs[kk][c + 2] = tf32_round(v.z);
            Bs[kk][c + 3] = tf32_round(v.w);
        }
        __syncthreads();

#pragma unroll
        for (int ks = 0; ks < 4; ks++) {
            const int k0 = ks * 8;
            uint32_t ah[4][4];
#pragma unroll
            for (int f = 0; f < 4; f++) {
                int r = wm * 64 + f * 16 + gid;
                ah[f][0] = __float_as_uint(As[r][k0 + tg]);
                ah[f][1] = __float_as_uint(As[r + 8][k0 + tg]);
                ah[f][2] = __float_as_uint(As[r][k0 + tg + 4]);
                ah[f][3] = __float_as_uint(As[r + 8][k0 + tg + 4]);
            }
            uint32_t bh[4][2];
#pragma unroll
            for (int n = 0; n < 4; n++) {
                int c = wn * 32 + n * 8 + gid;
                bh[n][0] = __float_as_uint(Bs[k0 + tg][c]);
                bh[n][1] = __float_as_uint(Bs[k0 + tg + 4][c]);
            }
#pragma unroll
            for (int f = 0; f < 4; f++)
#pragma unroll
                for (int n = 0; n < 4; n++)
                    mma_tf32(acc[f][n][0], acc[f][n][1], acc[f][n][2], acc[f][n][3],
                             ah[f][0], ah[f][1], ah[f][2], ah[f][3], bh[n][0], bh[n][1]);
        }
        __syncthreads();
    }

    // epilogue: c0/c1 at (row gid, col 2tg), c2/c3 at (row gid+8)
#pragma unroll
    for (int f = 0; f < 4; f++) {
        int r1 = row0 + wm * 64 + f * 16 + gid;
        int r2 = r1 + 8;
#pragma unroll
        for (int n = 0; n < 4; n++) {
            int c = wn * 32 + n * 8 + tg * 2;
            if (r1 < NN)
                *(float2*)&out[(size_t)r1 * NH + c] = make_float2(acc[f][n][0], acc[f][n][1]);
            if (r2 < NN)
                *(float2*)&out[(size_t)r2 * NH + c] = make_float2(acc[f][n][2], acc[f][n][3]);
        }
    }
}

// ---------------------------------------------------------------------------
// CSR build
// ---------------------------------------------------------------------------
__global__ void zero_deg_kernel(int* __restrict__ deg)
{
    int i = blockIdx.x * blockDim.x + threadIdx.x;
    if (i < NN) deg[i] = 0;
}

__global__ void hist_kernel(const int* __restrict__ er, int* __restrict__ deg, int E)
{
    int e = (blockIdx.x * blockDim.x + threadIdx.x) * 2;
    if (e + 1 < E) {
        int2 r2 = *(const int2*)&er[e];
        atomicAdd(&deg[r2.x], 1);
        atomicAdd(&deg[r2.y], 1);
    } else if (e < E) {
        atomicAdd(&deg[er[e]], 1);
    }
}

// exclusive scan over deg -> rowptr/cursor, single block, warp-shfl based.
__global__ __launch_bounds__(1024) void scan_kernel(
    const int* __restrict__ deg, int* __restrict__ rowptr,
    int* __restrict__ cursor)
{
    __shared__ int wsum[32];
    __shared__ int carry_s;
    const int t = threadIdx.x, lane = t & 31, w = t >> 5;
    if (t == 0) carry_s = 0;
    __syncthreads();

    for (int base = 0; base < NN; base += 4096) {
        int cbase = carry_s;
        int i = base + t * 4;
        int4 v = make_int4(0, 0, 0, 0);
        if (i < NN) v = *(const int4*)&deg[i];   // NN % 4 == 0
        int s = v.x + v.y + v.z + v.w;

        int inc = s;
#pragma unroll
        for (int o = 1; o < 32; o <<= 1) {
            int y = __shfl_up_sync(0xffffffffu, inc, o);
            if (lane >= o) inc += y;
        }
        if (lane == 31) wsum[w] = inc;
        __syncthreads();
        if (w == 0) {
            int ws = wsum[lane];
#pragma unroll
            for (int o = 1; o < 32; o <<= 1) {
                int y = __shfl_up_sync(0xffffffffu, ws, o);
                if (lane >= o) ws += y;
            }
            wsum[lane] = ws;
        }
        __syncthreads();

        int prefix = cbase + ((w > 0) ? wsum[w - 1] : 0) + (inc - s);
        if (i < NN) {
            int e0 = prefix;
            int e1 = e0 + v.x;
            int e2 = e1 + v.y;
            int e3 = e2 + v.z;
            int4 o4 = make_int4(e0, e1, e2, e3);
            *(int4*)&rowptr[i] = o4;
            *(int4*)&cursor[i] = o4;
        }
        __syncthreads();
        if (t == 0) carry_s += wsum[31];
        __syncthreads();
    }
    if (t == 0) rowptr[NN] = carry_s;
}

__global__ void scatter_kernel(
    const int* __restrict__ er, const int* __restrict__ ec,
    const float* __restrict__ ew, int* __restrict__ cursor,
    float2* __restrict__ edges, int E)
{
    int e = (blockIdx.x * blockDim.x + threadIdx.x) * 2;
    if (e + 1 < E) {
        int2   r2 = *(const int2*)&er[e];
        int2   c2 = *(const int2*)&ec[e];
        float2 w2 = *(const float2*)&ew[e];
        int p0 = atomicAdd(&cursor[r2.x], 1);
        edges[p0] = make_float2(__int_as_float(c2.x), w2.x);
        int p1 = atomicAdd(&cursor[r2.y], 1);
        edges[p1] = make_float2(__int_as_float(c2.y), w2.y);
    } else if (e < E) {
        int pos = atomicAdd(&cursor[er[e]], 1);
        edges[pos] = make_float2(__int_as_float(ec[e]), ew[e]);
    }
}

// ---------------------------------------------------------------------------
// SpMM1-CSR fused with bias + relu + dropout mask + GEMM2.  (R15 form, frozen)
// Block = 8 warps; each warp handles 4 consecutive rows (block = 32 rows).
// ---------------------------------------------------------------------------
__global__ __launch_bounds__(256) void spmm1_gemm2_kernel(
    const int* __restrict__ rowptr, const float2* __restrict__ edges,
    const float4* __restrict__ suppv, const float* __restrict__ b1,
    const float* __restrict__ mask, const float* __restrict__ W2,
    float* __restrict__ x2, float* __restrict__ supp2)
{
    __shared__ float sW2[NH * NC];   // 20 KB
    __shared__ float sx2[8][NH];     // 4 KB, one row per warp

    for (int i = threadIdx.x; i < NH * NC; i += blockDim.x) sW2[i] = W2[i];
    __syncthreads();

    const int wid  = threadIdx.x >> 5;
    const int lane = threadIdx.x & 31;

    float4 bb = *(const float4*)&b1[lane << 2];

#pragma unroll 1
    for (int r4 = 0; r4 < 4; r4++) {
        const int row = blockIdx.x * 32 + wid * 4 + r4;

        const int s = rowptr[row];
        const int e = rowptr[row + 1];

        float4 acc = make_float4(0.f, 0.f, 0.f, 0.f);
        int i = s;
        for (; i + 4 <= e; i += 4) {
            float2 ed0 = __ldg(&edges[i]);
            float2 ed1 = __ldg(&edges[i + 1]);
            float2 ed2 = __ldg(&edges[i + 2]);
            float2 ed3 = __ldg(&edges[i + 3]);
            float4 g0 = __ldg(&suppv[(size_t)__float_as_int(ed0.x) * (NH / 4) + lane]);
            float4 g1 = __ldg(&suppv[(size_t)__float_as_int(ed1.x) * (NH / 4) + lane]);
            float4 g2 = __ldg(&suppv[(size_t)__float_as_int(ed2.x) * (NH / 4) + lane]);
            float4 g3 = __ldg(&suppv[(size_t)__float_as_int(ed3.x) * (NH / 4) + lane]);
            acc.x = fmaf(ed0.y, g0.x, acc.x); acc.y = fmaf(ed0.y, g0.y, acc.y);
            acc.z = fmaf(ed0.y, g0.z, acc.z); acc.w = fmaf(ed0.y, g0.w, acc.w);
            acc.x = fmaf(ed1.y, g1.x, acc.x); acc.y = fmaf(ed1.y, g1.y, acc.y);
            acc.z = fmaf(ed1.y, g1.z, acc.z); acc.w = fmaf(ed1.y, g1.w, acc.w);
            acc.x = fmaf(ed2.y, g2.x, acc.x); acc.y = fmaf(ed2.y, g2.y, acc.y);
            acc.z = fmaf(ed2.y, g2.z, acc.z); acc.w = fmaf(ed2.y, g2.w, acc.w);
            acc.x = fmaf(ed3.y, g3.x, acc.x); acc.y = fmaf(ed3.y, g3.y, acc.y);
            acc.z = fmaf(ed3.y, g3.z, acc.z); acc.w = fmaf(ed3.y, g3.w, acc.w);
        }
        for (; i < e; i++) {
            float2 ed = __ldg(&edges[i]);
            float4 g = __ldg(&suppv[(size_t)__float_as_int(ed.x) * (NH / 4) + lane]);
            acc.x = fmaf(ed.y, g.x, acc.x); acc.y = fmaf(ed.y, g.y, acc.y);
            acc.z = fmaf(ed.y, g.z, acc.z); acc.w = fmaf(ed.y, g.w, acc.w);
        }

        float4 mm = *(const float4*)&mask[(size_t)row * NH + (lane << 2)];
        float4 r;
        r.x = fmaxf(acc.x + bb.x, 0.f) * mm.x;
        r.y = fmaxf(acc.y + bb.y, 0.f) * mm.y;
        r.z = fmaxf(acc.z + bb.z, 0.f) * mm.z;
        r.w = fmaxf(acc.w + bb.w, 0.f) * mm.w;
        *(float4*)&x2[(size_t)row * NH + (lane << 2)] = r;
        *(float4*)&sx2[wid][lane << 2] = r;
        __syncwarp();

        float acc1 = 0.0f, acc2 = 0.0f;
        const float* xr = sx2[wid];
#pragma unroll 8
        for (int k = 0; k < NH; k++) {
            float xv = xr[k];
            acc1 = fmaf(xv, sW2[k * NC + lane], acc1);
            if (lane < 8) acc2 = fmaf(xv, sW2[k * NC + 32 + lane], acc2);
        }
        supp2[(size_t)row * NC + lane] = acc1;
        if (lane < 8) supp2[(size_t)row * NC + 32 + lane] = acc2;
        __syncwarp();
    }
}

// ---------------------------------------------------------------------------
// SpMM2-CSR fused with bias + log_softmax.  (R10/R13 form, frozen)
// ---------------------------------------------------------------------------
__global__ __launch_bounds__(256) void spmm2_lsm_kernel(
    const int* __restrict__ rowptr, const float2* __restrict__ edges,
    const float4* __restrict__ suppv, const float* __restrict__ b2,
    float* __restrict__ out)
{
    const int warp = (blockIdx.x * blockDim.x + threadIdx.x) >> 5;
    if (warp >= NN) return;
    const int lane = threadIdx.x & 31;
    const int grp  = lane / 10;            // 0,1,2 active; 3 = lanes 30,31 idle
    const int cls  = lane - grp * 10;      // 0..9
    const bool in3 = (grp < 3);

    const int s = rowptr[warp];
    const int e = rowptr[warp + 1];

    float4 acc = make_float4(0.f, 0.f, 0.f, 0.f);
    if (in3) {
        for (int i = s + grp; i < e; i += 3) {
            float2 ed = __ldg(&edges[i]);
            float4 g = __ldg(&suppv[(size_t)__float_as_int(ed.x) * (NC / 4) + cls]);
            acc.x = fmaf(ed.y, g.x, acc.x); acc.y = fmaf(ed.y, g.y, acc.y);
            acc.z = fmaf(ed.y, g.z, acc.z); acc.w = fmaf(ed.y, g.w, acc.w);
        }
    }

    {
        float t1x = __shfl_down_sync(0xffffffffu, acc.x, 10);
        float t1y = __shfl_down_sync(0xffffffffu, acc.y, 10);
        float t1z = __shfl_down_sync(0xffffffffu, acc.z, 10);
        float t1w = __shfl_down_sync(0xffffffffu, acc.w, 10);
        float t2x = __shfl_down_sync(0xffffffffu, acc.x, 20);
        float t2y = __shfl_down_sync(0xffffffffu, acc.y, 20);
        float t2z = __shfl_down_sync(0xffffffffu, acc.z, 20);
        float t2w = __shfl_down_sync(0xffffffffu, acc.w, 20);
        acc.x += t1x + t2x;
        acc.y += t1y + t2y;
        acc.z += t1z + t2z;
        acc.w += t1w + t2w;
    }

    const bool act = (lane < 10);
    float4 v = make_float4(0.f, 0.f, 0.f, 0.f);
    float m = -3.4e38f;
    if (act) {
        float4 bb = *(const float4*)&b2[lane << 2];
        v.x = acc.x + bb.x; v.y = acc.y + bb.y;
        v.z = acc.z + bb.z; v.w = acc.w + bb.w;
        m = fmaxf(fmaxf(v.x, v.y), fmaxf(v.z, v.w));
    }
#pragma unroll
    for (int o = 16; o > 0; o >>= 1)
        m = fmaxf(m, __shfl_xor_sync(0xffffffffu, m, o));

    float sum = 0.f;
    if (act)
        sum = __expf(v.x - m) + __expf(v.y - m) + __expf(v.z - m) + __expf(v.w - m);
#pragma unroll
    for (int o = 16; o > 0; o >>= 1)
        sum += __shfl_xor_sync(0xffffffffu, sum, o);

    float lse = m + __logf(sum);
    if (act) {
        *(float4*)&out[(size_t)warp * NC + (lane << 2)] =
            make_float4(v.x - lse, v.y - lse, v.z - lse, v.w - lse);
    }
}

// ---------------------------------------------------------------------------
extern "C" void kernel_launch(void* const* d_in, const int* in_sizes, int n_in,
                              void* d_out, int out_size)
{
    const float* x    = (const float*)d_in[0];
    const int*   er   = (const int*)  d_in[1];
    const int*   ec   = (const int*)  d_in[2];
    const float* ew   = (const float*)d_in[3];
    const float* W1   = (const float*)d_in[4];
    const float* b1   = (const float*)d_in[5];
    const float* W2   = (const float*)d_in[6];
    const float* b2   = (const float*)d_in[7];
    const float* mask = (const float*)d_in[8];
    const int E = in_sizes[1];

    float* out_lsm = (float*)d_out;                   // [N, 40]
    float* out_x2  = (float*)d_out + (size_t)NN * NC; // [N, 128]

    float *supp1, *supp2; float2* edges; int *rowptr, *cursor, *deg;
    cudaGetSymbolAddress((void**)&supp1,  g_supp1);
    cudaGetSymbolAddress((void**)&supp2,  g_supp2);
    cudaGetSymbolAddress((void**)&edges,  g_edges);
    cudaGetSymbolAddress((void**)&rowptr, g_rowptr);
    cudaGetSymbolAddress((void**)&cursor, g_cursor);
    cudaGetSymbolAddress((void**)&deg,    g_deg);

    const bool fork = (g_s1 != nullptr);
    cudaStream_t s1 = fork ? g_s1 : (cudaStream_t)0;

    // Fork: CSR build on side stream, gemm1 on main (null) stream.
    if (fork) {
        cudaEventRecord(g_ev_fork, 0);
        cudaStreamWaitEvent(s1, g_ev_fork, 0);
    }

    zero_deg_kernel<<<(NN + 255) / 256, 256, 0, s1>>>(deg);
    hist_kernel<<<(E / 2 + 255) / 256, 256, 0, s1>>>(er, deg, E);
    scan_kernel<<<1, 1024, 0, s1>>>(deg, rowptr, cursor);
    scatter_kernel<<<(E / 2 + 255) / 256, 256, 0, s1>>>(er, ec, ew, cursor, edges, E);

    gemm1_kernel<<<(NN + 127) / 128, 256>>>(x, W1, supp1);

    // Join before spmm1 (needs both supp1 and CSR).
    if (fork) {
        cudaEventRecord(g_ev_join, s1);
        cudaStreamWaitEvent(0, g_ev_join, 0);
    }

    // spmm1 + gemm2 fused: writes x2 (d_out) and supp2 in one pass.
    spmm1_gemm2_kernel<<<NN / 32, 256>>>(
        rowptr, edges, (const float4*)supp1, b1, mask, W2, out_x2, supp2);

    spmm2_lsm_kernel<<<(NN * 32 + 255) / 256, 256>>>(
        rowptr, edges, (const float4*)supp2, b2, out_lsm);
}

// round 17
// speedup vs baseline: 1.3833x; 1.0459x over previous
#include <cuda_runtime.h>
#include <cstdint>

// Problem constants (fixed by the reference)
#define NN 100000
#define NF 512
#define NH 128
#define NC 40
#define EMAX 3200000

// Scratch (device globals; no allocation allowed)
__device__ float  g_supp1[NN * NH];     // x @ W1          51.2 MB
__device__ float  g_supp2[NN * NC];     // x2 @ W2         16 MB
__device__ float2 g_edges[EMAX];        // CSR (col,w)     25.6 MB
__device__ int    g_rowptr[NN + 1];
__device__ int    g_cursor[NN];
__device__ int    g_deg[NN];

// Side stream + fork/join events, created at program init.
static cudaStream_t g_s1 = nullptr;
static cudaEvent_t  g_ev_fork = nullptr, g_ev_join = nullptr;
namespace {
struct StreamInit {
    StreamInit() {
        cudaStreamCreateWithFlags(&g_s1, cudaStreamNonBlocking);
        cudaEventCreateWithFlags(&g_ev_fork, cudaEventDisableTiming);
        cudaEventCreateWithFlags(&g_ev_join, cudaEventDisableTiming);
    }
};
static StreamInit g_stream_init;
}

__device__ __forceinline__ float tf32_round(float v) {
    uint32_t u;
    asm("cvt.rna.tf32.f32 %0, %1;" : "=r"(u) : "f"(v));
    return __uint_as_float(u);
}

__device__ __forceinline__ void mma_tf32(float& d0, float& d1, float& d2, float& d3,
                                         uint32_t a0, uint32_t a1, uint32_t a2, uint32_t a3,
                                         uint32_t b0, uint32_t b1) {
    asm volatile(
        "mma.sync.aligned.m16n8k8.row.col.f32.tf32.tf32.f32 "
        "{%0,%1,%2,%3}, {%4,%5,%6,%7}, {%8,%9}, {%0,%1,%2,%3};"
        : "+f"(d0), "+f"(d1), "+f"(d2), "+f"(d3)
        : "r"(a0), "r"(a1), "r"(a2), "r"(a3), "r"(b0), "r"(b1));
}

// ---------------------------------------------------------------------------
// GEMM1 (tensor cores, single-pass tf32 mma.sync), BK=64 (dynamic smem):
//   supp1[N,128] = x[N,512] @ W1[512,128]
// CTA tile M=128 x N=128, BK=64 (8 chunks). 8 warps as 2 (M) x 4 (N).
// Warp tile 64x32 -> 4 m-frags (m16) x 4 n-frags (n8); 8 k-steps per chunk.
// Same k-step MMA sequence as R14/R16 -> bit-identical supp1.
// SMEM: As[128][68] (34816 B) + Bs[64][136] (34816 B) = 69632 B dynamic.
// ---------------------------------------------------------------------------
#define APAD 68
#define BPAD 136
#define G1_SMEM (128 * APAD * 4 + 64 * BPAD * 4)   // 69632

__global__ __launch_bounds__(256, 1) void gemm1_kernel(
    const float* __restrict__ x, const float* __restrict__ W1,
    float* __restrict__ out)
{
    extern __shared__ float smem_dyn[];
    float (*As)[APAD] = (float(*)[APAD])smem_dyn;                  // [128][68]
    float (*Bs)[BPAD] = (float(*)[BPAD])(smem_dyn + 128 * APAD);   // [64][136]

    const int tid = threadIdx.x;
    const int wid = tid >> 5;
    const int lane = tid & 31;
    const int gid = lane >> 2;     // group id 0..7
    const int tg  = lane & 3;      // thread-in-group 0..3
    const int wm = wid >> 2;       // 0..1 -> rows wm*64
    const int wn = wid & 3;        // 0..3 -> cols wn*32
    const int row0 = blockIdx.x * 128;

    float acc[4][4][4];
#pragma unroll
    for (int f = 0; f < 4; f++)
#pragma unroll
        for (int n = 0; n < 4; n++)
#pragma unroll
            for (int q = 0; q < 4; q++) acc[f][n][q] = 0.0f;

    for (int ch = 0; ch < NF / 64; ch++) {
        // ---- stage A chunk: x[row0..row0+128)[ch*64..+64), tf32-rounded
        // 128 rows x 64 k = 2048 float4, 8 per thread
#pragma unroll
        for (int j = 0; j < 8; j++) {
            int i = tid + j * 256;
            int r = i >> 4;               // 16 float4 per row
            int kq = (i & 15) << 2;
            float4 v = make_float4(0.f, 0.f, 0.f, 0.f);
            if (row0 + r < NN)
                v = *(const float4*)&x[(size_t)(row0 + r) * NF + ch * 64 + kq];
            As[r][kq + 0] = tf32_round(v.x);
            As[r][kq + 1] = tf32_round(v.y);
            As[r][kq + 2] = tf32_round(v.z);
            As[r][kq + 3] = tf32_round(v.w);
        }
        // ---- stage B chunk: W1[ch*64..+64)[0..128), tf32-rounded
        // 64 k x 128 cols = 2048 float4, 8 per thread
#pragma unroll
        for (int j = 0; j < 8; j++) {
            int i = tid + j * 256;
            int kk = i >> 5;
            int c = (i & 31) << 2;
            float4 v = *(const float4*)&W1[(size_t)(ch * 64 + kk) * NH + c];
            Bs[kk][c + 0] = tf32_round(v.x);
            Bs[kk][c + 1] = tf32_round(v.y);
            Bs[kk][c + 2] = tf32_round(v.z);
            Bs[kk][c + 3] = tf32_round(v.w);
        }
        __syncthreads();

#pragma unroll
        for (int ks = 0; ks < 8; ks++) {
            const int k0 = ks * 8;
            uint32_t ah[4][4];
#pragma unroll
            for (int f = 0; f < 4; f++) {
                int r = wm * 64 + f * 16 + gid;
                ah[f][0] = __float_as_uint(As[r][k0 + tg]);
                ah[f][1] = __float_as_uint(As[r + 8][k0 + tg]);
                ah[f][2] = __float_as_uint(As[r][k0 + tg + 4]);
                ah[f][3] = __float_as_uint(As[r + 8][k0 + tg + 4]);
            }
            uint32_t bh[4][2];
#pragma unroll
            for (int n = 0; n < 4; n++) {
                int c = wn * 32 + n * 8 + gid;
                bh[n][0] = __float_as_uint(Bs[k0 + tg][c]);
                bh[n][1] = __float_as_uint(Bs[k0 + tg + 4][c]);
            }
#pragma unroll
            for (int f = 0; f < 4; f++)
#pragma unroll
                for (int n = 0; n < 4; n++)
                    mma_tf32(acc[f][n][0], acc[f][n][1], acc[f][n][2], acc[f][n][3],
                             ah[f][0], ah[f][1], ah[f][2], ah[f][3], bh[n][0], bh[n][1]);
        }
        __syncthreads();
    }

    // epilogue: c0/c1 at (row gid, col 2tg), c2/c3 at (row gid+8)
#pragma unroll
    for (int f = 0; f < 4; f++) {
        int r1 = row0 + wm * 64 + f * 16 + gid;
        int r2 = r1 + 8;
#pragma unroll
        for (int n = 0; n < 4; n++) {
            int c = wn * 32 + n * 8 + tg * 2;
            if (r1 < NN)
                *(float2*)&out[(size_t)r1 * NH + c] = make_float2(acc[f][n][0], acc[f][n][1]);
            if (r2 < NN)
                *(float2*)&out[(size_t)r2 * NH + c] = make_float2(acc[f][n][2], acc[f][n][3]);
        }
    }
}

// ---------------------------------------------------------------------------
// CSR build
// ---------------------------------------------------------------------------
__global__ void zero_deg_kernel(int* __restrict__ deg)
{
    int i = blockIdx.x * blockDim.x + threadIdx.x;
    if (i < NN) deg[i] = 0;
}

__global__ void hist_kernel(const int* __restrict__ er, int* __restrict__ deg, int E)
{
    int e = (blockIdx.x * blockDim.x + threadIdx.x) * 2;
    if (e + 1 < E) {
        int2 r2 = *(const int2*)&er[e];
        atomicAdd(&deg[r2.x], 1);
        atomicAdd(&deg[r2.y], 1);
    } else if (e < E) {
        atomicAdd(&deg[er[e]], 1);
    }
}

// exclusive scan over deg -> rowptr/cursor, single block, warp-shfl based.
__global__ __launch_bounds__(1024) void scan_kernel(
    const int* __restrict__ deg, int* __restrict__ rowptr,
    int* __restrict__ cursor)
{
    __shared__ int wsum[32];
    __shared__ int carry_s;
    const int t = threadIdx.x, lane = t & 31, w = t >> 5;
    if (t == 0) carry_s = 0;
    __syncthreads();

    for (int base = 0; base < NN; base += 4096) {
        int cbase = carry_s;
        int i = base + t * 4;
        int4 v = make_int4(0, 0, 0, 0);
        if (i < NN) v = *(const int4*)&deg[i];   // NN % 4 == 0
        int s = v.x + v.y + v.z + v.w;

        int inc = s;
#pragma unroll
        for (int o = 1; o < 32; o <<= 1) {
            int y = __shfl_up_sync(0xffffffffu, inc, o);
            if (lane >= o) inc += y;
        }
        if (lane == 31) wsum[w] = inc;
        __syncthreads();
        if (w == 0) {
            int ws = wsum[lane];
#pragma unroll
            for (int o = 1; o < 32; o <<= 1) {
                int y = __shfl_up_sync(0xffffffffu, ws, o);
                if (lane >= o) ws += y;
            }
            wsum[lane] = ws;
        }
        __syncthreads();

        int prefix = cbase + ((w > 0) ? wsum[w - 1] : 0) + (inc - s);
        if (i < NN) {
            int e0 = prefix;
            int e1 = e0 + v.x;
            int e2 = e1 + v.y;
            int e3 = e2 + v.z;
            int4 o4 = make_int4(e0, e1, e2, e3);
            *(int4*)&rowptr[i] = o4;
            *(int4*)&cursor[i] = o4;
        }
        __syncthreads();
        if (t == 0) carry_s += wsum[31];
        __syncthreads();
    }
    if (t == 0) rowptr[NN] = carry_s;
}

__global__ void scatter_kernel(
    const int* __restrict__ er, const int* __restrict__ ec,
    const float* __restrict__ ew, int* __restrict__ cursor,
    float2* __restrict__ edges, int E)
{
    int e = (blockIdx.x * blockDim.x + threadIdx.x) * 2;
    if (e + 1 < E) {
        int2   r2 = *(const int2*)&er[e];
        int2   c2 = *(const int2*)&ec[e];
        float2 w2 = *(const float2*)&ew[e];
        int p0 = atomicAdd(&cursor[r2.x], 1);
        edges[p0] = make_float2(__int_as_float(c2.x), w2.x);
        int p1 = atomicAdd(&cursor[r2.y], 1);
        edges[p1] = make_float2(__int_as_float(c2.y), w2.y);
    } else if (e < E) {
        int pos = atomicAdd(&cursor[er[e]], 1);
        edges[pos] = make_float2(__int_as_float(ec[e]), ew[e]);
    }
}

// ---------------------------------------------------------------------------
// SpMM1-CSR fused with bias + relu + dropout mask + GEMM2.  (R15 form, frozen)
// Block = 8 warps; each warp handles 4 consecutive rows (block = 32 rows).
// ---------------------------------------------------------------------------
__global__ __launch_bounds__(256) void spmm1_gemm2_kernel(
    const int* __restrict__ rowptr, const float2* __restrict__ edges,
    const float4* __restrict__ suppv, const float* __restrict__ b1,
    const float* __restrict__ mask, const float* __restrict__ W2,
    float* __restrict__ x2, float* __restrict__ supp2)
{
    __shared__ float sW2[NH * NC];   // 20 KB
    __shared__ float sx2[8][NH];     // 4 KB, one row per warp

    for (int i = threadIdx.x; i < NH * NC; i += blockDim.x) sW2[i] = W2[i];
    __syncthreads();

    const int wid  = threadIdx.x >> 5;
    const int lane = threadIdx.x & 31;

    float4 bb = *(const float4*)&b1[lane << 2];

#pragma unroll 1
    for (int r4 = 0; r4 < 4; r4++) {
        const int row = blockIdx.x * 32 + wid * 4 + r4;

        const int s = rowptr[row];
        const int e = rowptr[row + 1];

        float4 acc = make_float4(0.f, 0.f, 0.f, 0.f);
        int i = s;
        for (; i + 4 <= e; i += 4) {
            float2 ed0 = __ldg(&edges[i]);
            float2 ed1 = __ldg(&edges[i + 1]);
            float2 ed2 = __ldg(&edges[i + 2]);
            float2 ed3 = __ldg(&edges[i + 3]);
            float4 g0 = __ldg(&suppv[(size_t)__float_as_int(ed0.x) * (NH / 4) + lane]);
            float4 g1 = __ldg(&suppv[(size_t)__float_as_int(ed1.x) * (NH / 4) + lane]);
            float4 g2 = __ldg(&suppv[(size_t)__float_as_int(ed2.x) * (NH / 4) + lane]);
            float4 g3 = __ldg(&suppv[(size_t)__float_as_int(ed3.x) * (NH / 4) + lane]);
            acc.x = fmaf(ed0.y, g0.x, acc.x); acc.y = fmaf(ed0.y, g0.y, acc.y);
            acc.z = fmaf(ed0.y, g0.z, acc.z); acc.w = fmaf(ed0.y, g0.w, acc.w);
            acc.x = fmaf(ed1.y, g1.x, acc.x); acc.y = fmaf(ed1.y, g1.y, acc.y);
            acc.z = fmaf(ed1.y, g1.z, acc.z); acc.w = fmaf(ed1.y, g1.w, acc.w);
            acc.x = fmaf(ed2.y, g2.x, acc.x); acc.y = fmaf(ed2.y, g2.y, acc.y);
            acc.z = fmaf(ed2.y, g2.z, acc.z); acc.w = fmaf(ed2.y, g2.w, acc.w);
            acc.x = fmaf(ed3.y, g3.x, acc.x); acc.y = fmaf(ed3.y, g3.y, acc.y);
            acc.z = fmaf(ed3.y, g3.z, acc.z); acc.w = fmaf(ed3.y, g3.w, acc.w);
        }
        for (; i < e; i++) {
            float2 ed = __ldg(&edges[i]);
            float4 g = __ldg(&suppv[(size_t)__float_as_int(ed.x) * (NH / 4) + lane]);
            acc.x = fmaf(ed.y, g.x, acc.x); acc.y = fmaf(ed.y, g.y, acc.y);
            acc.z = fmaf(ed.y, g.z, acc.z); acc.w = fmaf(ed.y, g.w, acc.w);
        }

        float4 mm = *(const float4*)&mask[(size_t)row * NH + (lane << 2)];
        float4 r;
        r.x = fmaxf(acc.x + bb.x, 0.f) * mm.x;
        r.y = fmaxf(acc.y + bb.y, 0.f) * mm.y;
        r.z = fmaxf(acc.z + bb.z, 0.f) * mm.z;
        r.w = fmaxf(acc.w + bb.w, 0.f) * mm.w;
        *(float4*)&x2[(size_t)row * NH + (lane << 2)] = r;
        *(float4*)&sx2[wid][lane << 2] = r;
        __syncwarp();

        float acc1 = 0.0f, acc2 = 0.0f;
        const float* xr = sx2[wid];
#pragma unroll 8
        for (int k = 0; k < NH; k++) {
            float xv = xr[k];
            acc1 = fmaf(xv, sW2[k * NC + lane], acc1);
            if (lane < 8) acc2 = fmaf(xv, sW2[k * NC + 32 + lane], acc2);
        }
        supp2[(size_t)row * NC + lane] = acc1;
        if (lane < 8) supp2[(size_t)row * NC + 32 + lane] = acc2;
        __syncwarp();
    }
}

// ---------------------------------------------------------------------------
// SpMM2-CSR fused with bias + log_softmax.  (R10/R13 form, frozen)
// ---------------------------------------------------------------------------
__global__ __launch_bounds__(256) void spmm2_lsm_kernel(
    const int* __restrict__ rowptr, const float2* __restrict__ edges,
    const float4* __restrict__ suppv, const float* __restrict__ b2,
    float* __restrict__ out)
{
    const int warp = (blockIdx.x * blockDim.x + threadIdx.x) >> 5;
    if (warp >= NN) return;
    const int lane = threadIdx.x & 31;
    const int grp  = lane / 10;            // 0,1,2 active; 3 = lanes 30,31 idle
    const int cls  = lane - grp * 10;      // 0..9
    const bool in3 = (grp < 3);

    const int s = rowptr[warp];
    const int e = rowptr[warp + 1];

    float4 acc = make_float4(0.f, 0.f, 0.f, 0.f);
    if (in3) {
        for (int i = s + grp; i < e; i += 3) {
            float2 ed = __ldg(&edges[i]);
            float4 g = __ldg(&suppv[(size_t)__float_as_int(ed.x) * (NC / 4) + cls]);
            acc.x = fmaf(ed.y, g.x, acc.x); acc.y = fmaf(ed.y, g.y, acc.y);
            acc.z = fmaf(ed.y, g.z, acc.z); acc.w = fmaf(ed.y, g.w, acc.w);
        }
    }

    {
        float t1x = __shfl_down_sync(0xffffffffu, acc.x, 10);
        float t1y = __shfl_down_sync(0xffffffffu, acc.y, 10);
        float t1z = __shfl_down_sync(0xffffffffu, acc.z, 10);
        float t1w = __shfl_down_sync(0xffffffffu, acc.w, 10);
        float t2x = __shfl_down_sync(0xffffffffu, acc.x, 20);
        float t2y = __shfl_down_sync(0xffffffffu, acc.y, 20);
        float t2z = __shfl_down_sync(0xffffffffu, acc.z, 20);
        float t2w = __shfl_down_sync(0xffffffffu, acc.w, 20);
        acc.x += t1x + t2x;
        acc.y += t1y + t2y;
        acc.z += t1z + t2z;
        acc.w += t1w + t2w;
    }

    const bool act = (lane < 10);
    float4 v = make_float4(0.f, 0.f, 0.f, 0.f);
    float m = -3.4e38f;
    if (act) {
        float4 bb = *(const float4*)&b2[lane << 2];
        v.x = acc.x + bb.x; v.y = acc.y + bb.y;
        v.z = acc.z + bb.z; v.w = acc.w + bb.w;
        m = fmaxf(fmaxf(v.x, v.y), fmaxf(v.z, v.w));
    }
#pragma unroll
    for (int o = 16; o > 0; o >>= 1)
        m = fmaxf(m, __shfl_xor_sync(0xffffffffu, m, o));

    float sum = 0.f;
    if (act)
        sum = __expf(v.x - m) + __expf(v.y - m) + __expf(v.z - m) + __expf(v.w - m);
#pragma unroll
    for (int o = 16; o > 0; o >>= 1)
        sum += __shfl_xor_sync(0xffffffffu, sum, o);

    float lse = m + __logf(sum);
    if (act) {
        *(float4*)&out[(size_t)warp * NC + (lane << 2)] =
            make_float4(v.x - lse, v.y - lse, v.z - lse, v.w - lse);
    }
}

// ---------------------------------------------------------------------------
extern "C" void kernel_launch(void* const* d_in, const int* in_sizes, int n_in,
                              void* d_out, int out_size)
{
    const float* x    = (const float*)d_in[0];
    const int*   er   = (const int*)  d_in[1];
    const int*   ec   = (const int*)  d_in[2];
    const float* ew   = (const float*)d_in[3];
    const float* W1   = (const float*)d_in[4];
    const float* b1   = (const float*)d_in[5];
    const float* W2   = (const float*)d_in[6];
    const float* b2   = (const float*)d_in[7];
    const float* mask = (const float*)d_in[8];
    const int E = in_sizes[1];

    float* out_lsm = (float*)d_out;                   // [N, 40]
    float* out_x2  = (float*)d_out + (size_t)NN * NC; // [N, 128]

    float *supp1, *supp2; float2* edges; int *rowptr, *cursor, *deg;
    cudaGetSymbolAddress((void**)&supp1,  g_supp1);
    cudaGetSymbolAddress((void**)&supp2,  g_supp2);
    cudaGetSymbolAddress((void**)&edges,  g_edges);
    cudaGetSymbolAddress((void**)&rowptr, g_rowptr);
    cudaGetSymbolAddress((void**)&cursor, g_cursor);
    cudaGetSymbolAddress((void**)&deg,    g_deg);

    const bool fork = (g_s1 != nullptr);
    cudaStream_t s1 = fork ? g_s1 : (cudaStream_t)0;

    // Fork: CSR build on side stream, gemm1 on main (null) stream.
    if (fork) {
        cudaEventRecord(g_ev_fork, 0);
        cudaStreamWaitEvent(s1, g_ev_fork, 0);
    }

    zero_deg_kernel<<<(NN + 255) / 256, 256, 0, s1>>>(deg);
    hist_kernel<<<(E / 2 + 255) / 256, 256, 0, s1>>>(er, deg, E);
    scan_kernel<<<1, 1024, 0, s1>>>(deg, rowptr, cursor);
    scatter_kernel<<<(E / 2 + 255) / 256, 256, 0, s1>>>(er, ec, ew, cursor, edges, E);

    cudaFuncSetAttribute(gemm1_kernel,
                         cudaFuncAttributeMaxDynamicSharedMemorySize, G1_SMEM);
    gemm1_kernel<<<(NN + 127) / 128, 256, G1_SMEM>>>(x, W1, supp1);

    // Join before spmm1 (needs both supp1 and CSR).
    if (fork) {
        cudaEventRecord(g_ev_join, s1);
        cudaStreamWaitEvent(0, g_ev_join, 0);
    }

    // spmm1 + gemm2 fused: writes x2 (d_out) and supp2 in one pass.
    spmm1_gemm2_kernel<<<NN / 32, 256>>>(
        rowptr, edges, (const float4*)supp1, b1, mask, W2, out_x2, supp2);

    spmm2_lsm_kernel<<<(NN * 32 + 255) / 256, 256>>>(
        rowptr, edges, (const float4*)supp2, b2, out_lsm);
}